// round 12
// baseline (speedup 1.0000x reference)
#include <cuda_runtime.h>
#include <cuda_bf16.h>
#include <cstdint>

// ---------------------------------------------------------------------------
// TransformerBlock: windowed attention, B=4 C=192 H=W=256, 16x16 windows.
//   K0 : prepass — split W_qk (bf16 hi/lo packed), convert W_v/W_proj to tf32
//   K1a: qk GEMM, grid (3, 1024), 512 thr, M=128 tiles (3x bf16)
//   K1b: v GEMM, grid (3, 1024), 256 thr (1x tf32)
//   K2 : attention + fused proj, grid (4, 1024), 512 thr
// q/k stored as packed bf16 hi/lo planes [win][ch][tok/2]; v tf32 [win][ch][tok].
// ---------------------------------------------------------------------------

constexpr int C_     = 192;
constexpr int NTOK   = 256;
constexpr int NWIN   = 1024;
constexpr int IMG    = 256 * 256;

__device__ uint32_t g_qh[(size_t)NWIN * C_ * 128];
__device__ uint32_t g_ql[(size_t)NWIN * C_ * 128];
__device__ uint32_t g_kh[(size_t)NWIN * C_ * 128];
__device__ uint32_t g_kl[(size_t)NWIN * C_ * 128];
__device__ uint32_t g_v [(size_t)NWIN * C_ * NTOK];   // tf32 bits [win][ch][tok]
__device__ uint32_t g_wqkh[384 * 96];
__device__ uint32_t g_wqkl[384 * 96];
__device__ uint32_t g_wv[192 * 192];   // W_v  as tf32 bits
__device__ uint32_t g_wp[192 * 192];   // W_proj as tf32 bits

__device__ __forceinline__ uint32_t f2tf(float x) {
    uint32_t u;
    asm("cvt.rna.tf32.f32 %0, %1;" : "=r"(u) : "f"(x));
    return u;
}
__device__ __forceinline__ void splitbf2(float x0, float x1, uint32_t& hi, uint32_t& lo) {
    __nv_bfloat16 h0 = __float2bfloat16_rn(x0);
    __nv_bfloat16 h1 = __float2bfloat16_rn(x1);
    __nv_bfloat16 l0 = __float2bfloat16_rn(x0 - __bfloat162float(h0));
    __nv_bfloat16 l1 = __float2bfloat16_rn(x1 - __bfloat162float(h1));
    hi = ((uint32_t)__bfloat16_as_ushort(h1) << 16) | __bfloat16_as_ushort(h0);
    lo = ((uint32_t)__bfloat16_as_ushort(l1) << 16) | __bfloat16_as_ushort(l0);
}
__device__ __forceinline__ uint32_t sptr(const void* p) {
    return (uint32_t)__cvta_generic_to_shared(p);
}
__device__ __forceinline__ void ldsm4(uint32_t* r, uint32_t a) {
    asm volatile("ldmatrix.sync.aligned.m8n8.x4.shared.b16 {%0,%1,%2,%3}, [%4];"
        : "=r"(r[0]), "=r"(r[1]), "=r"(r[2]), "=r"(r[3]) : "r"(a));
}
__device__ __forceinline__ void ldsm2(uint32_t* r, uint32_t a) {
    asm volatile("ldmatrix.sync.aligned.m8n8.x2.shared.b16 {%0,%1}, [%2];"
        : "=r"(r[0]), "=r"(r[1]) : "r"(a));
}
__device__ __forceinline__ void ldsm4t(uint32_t* r, uint32_t a) {
    asm volatile("ldmatrix.sync.aligned.m8n8.x4.trans.shared.b16 {%0,%1,%2,%3}, [%4];"
        : "=r"(r[0]), "=r"(r[1]), "=r"(r[2]), "=r"(r[3]) : "r"(a));
}
__device__ __forceinline__ void mma8(float* d, const uint32_t* a, const uint32_t* b) {
    asm volatile(
        "mma.sync.aligned.m16n8k8.row.col.f32.tf32.tf32.f32 "
        "{%0,%1,%2,%3}, {%4,%5,%6,%7}, {%8,%9}, {%0,%1,%2,%3};\n"
        : "+f"(d[0]), "+f"(d[1]), "+f"(d[2]), "+f"(d[3])
        : "r"(a[0]), "r"(a[1]), "r"(a[2]), "r"(a[3]),
          "r"(b[0]), "r"(b[1]));
}
__device__ __forceinline__ void mma16(float* d, const uint32_t* a, const uint32_t* b) {
    asm volatile(
        "mma.sync.aligned.m16n8k16.row.col.f32.bf16.bf16.f32 "
        "{%0,%1,%2,%3}, {%4,%5,%6,%7}, {%8,%9}, {%0,%1,%2,%3};\n"
        : "+f"(d[0]), "+f"(d[1]), "+f"(d[2]), "+f"(d[3])
        : "r"(a[0]), "r"(a[1]), "r"(a[2]), "r"(a[3]),
          "r"(b[0]), "r"(b[1]));
}

// ===========================================================================
// K0: prepass — split W_qk; convert W_v and W_proj to tf32 bits.
// ===========================================================================
__global__ void split_w_kernel(const float* __restrict__ qkv_w,
                               const float* __restrict__ proj_w) {
    int idx = blockIdx.x * 256 + threadIdx.x;
    if (idx < 384 * 96) {
        int r = idx / 96, c = idx % 96;
        uint32_t h, l;
        splitbf2(qkv_w[r * C_ + 2 * c], qkv_w[r * C_ + 2 * c + 1], h, l);
        g_wqkh[idx] = h;
        g_wqkl[idx] = l;
    } else if (idx < 384 * 96 + 192 * 192) {
        int j = idx - 384 * 96;
        g_wv[j] = f2tf(qkv_w[384 * 192 + j]);
    } else if (idx < 384 * 96 + 2 * 192 * 192) {
        int j = idx - 384 * 96 - 192 * 192;
        g_wp[j] = f2tf(proj_w[j]);
    }
}

// ===========================================================================
// K1a: qk GEMM (3x bf16). grid (3, 1024), 512 thr, M=128, 2 CTA/SM.
// smem: Ah/Al [128][20] words + Bh/Bl [32][264] b16 = 54272 B
// ===========================================================================
constexpr int AQK = 20;
constexpr int BT16 = 264;
constexpr size_t SMEM_QK_BYTES = (size_t)(2 * 128 * AQK + 2 * 32 * 132) * 4;  // 54272

__global__ void __launch_bounds__(512, 2) qk_kernel(const float* __restrict__ x,
                                                    const float* __restrict__ qkv_b) {
    extern __shared__ uint32_t smq[];
    uint32_t* Ah = smq;
    uint32_t* Al = Ah + 128 * AQK;
    uint16_t* Bh16 = (uint16_t*)(smq + 2 * 128 * AQK);
    uint16_t* Bl16 = Bh16 + 32 * BT16;

    const int m0 = blockIdx.x * 128;
    const int w  = blockIdx.y;
    const int b  = w >> 8, wh = (w >> 4) & 15, ww = w & 15;
    const int tid = threadIdx.x, warp = tid >> 5, lane = tid & 31;
    const int wm = (warp >> 2) << 5;     // 0,32,64,96
    const int wn = (warp & 3) << 6;      // 0,64,128,192
    const float* xw = x + (size_t)b * C_ * IMG + (size_t)(wh * 16) * 256 + ww * 16;

    float acc[2][8][4];
#pragma unroll
    for (int i = 0; i < 2; i++)
#pragma unroll
        for (int j = 0; j < 8; j++)
#pragma unroll
            for (int r = 0; r < 4; r++) acc[i][j][r] = 0.f;

    const int arow = wm + (lane & 7) + ((lane & 8) ? 8 : 0);
    const int asel = (lane & 16) ? 4 : 0;
    const int brow0 = (lane & 7) + ((lane & 8) ? 8 : 0);
    const int bsel = (lane & 16) ? 8 : 0;

    for (int k0 = 0; k0 < C_; k0 += 32) {
        const int kw0 = k0 >> 1;
        // A: copy pre-split planes (128 rows x 16 words each plane)
#pragma unroll
        for (int t = tid; t < 512; t += 512) {
            int r = t >> 2, c4 = (t & 3) << 2;
            *reinterpret_cast<uint4*>(&Ah[r * AQK + c4]) =
                *reinterpret_cast<const uint4*>(&g_wqkh[(m0 + r) * 96 + kw0 + c4]);
            *reinterpret_cast<uint4*>(&Al[r * AQK + c4]) =
                *reinterpret_cast<const uint4*>(&g_wqkl[(m0 + r) * 96 + kw0 + c4]);
        }
        // B: x window -> bf16 hi/lo [ch][tok]
#pragma unroll
        for (int t = tid; t < 1024; t += 512) {
            int kp = t >> 6, q = t & 63;
            int i = q >> 2, j4 = (q & 3) << 2;
            const float* p0 = xw + (size_t)(k0 + 2 * kp) * IMG + i * 256 + j4;
            float4 v0 = *reinterpret_cast<const float4*>(p0);
            float4 v1 = *reinterpret_cast<const float4*>(p0 + IMG);
            int tok = i * 16 + j4;
            uint32_t h, l;
            uint32_t* dh0 = reinterpret_cast<uint32_t*>(&Bh16[(2 * kp) * BT16 + tok]);
            uint32_t* dl0 = reinterpret_cast<uint32_t*>(&Bl16[(2 * kp) * BT16 + tok]);
            uint32_t* dh1 = reinterpret_cast<uint32_t*>(&Bh16[(2 * kp + 1) * BT16 + tok]);
            uint32_t* dl1 = reinterpret_cast<uint32_t*>(&Bl16[(2 * kp + 1) * BT16 + tok]);
            splitbf2(v0.x, v0.y, h, l); dh0[0] = h; dl0[0] = l;
            splitbf2(v0.z, v0.w, h, l); dh0[1] = h; dl0[1] = l;
            splitbf2(v1.x, v1.y, h, l); dh1[0] = h; dl1[0] = l;
            splitbf2(v1.z, v1.w, h, l); dh1[1] = h; dl1[1] = l;
        }
        __syncthreads();

#pragma unroll
        for (int kk = 0; kk < 32; kk += 16) {
            uint32_t ah[2][4], al[2][4];
            int awrd = (kk >> 1) + asel;
            ldsm4(ah[0], sptr(&Ah[arow * AQK + awrd]));
            ldsm4(ah[1], sptr(&Ah[(arow + 16) * AQK + awrd]));
            ldsm4(al[0], sptr(&Al[arow * AQK + awrd]));
            ldsm4(al[1], sptr(&Al[(arow + 16) * AQK + awrd]));
            int brow = kk + brow0;
#pragma unroll
            for (int inp = 0; inp < 4; inp++) {
                int n0 = wn + inp * 16 + bsel;
                uint32_t bh4[4], bl4[4];
                ldsm4t(bh4, sptr(&Bh16[brow * BT16 + n0]));
                ldsm4t(bl4, sptr(&Bl16[brow * BT16 + n0]));
#pragma unroll
                for (int im = 0; im < 2; im++) {
                    mma16(acc[im][2 * inp],     ah[im], bl4);
                    mma16(acc[im][2 * inp],     al[im], bh4);
                    mma16(acc[im][2 * inp],     ah[im], bh4);
                    mma16(acc[im][2 * inp + 1], ah[im], bl4 + 2);
                    mma16(acc[im][2 * inp + 1], al[im], bh4 + 2);
                    mma16(acc[im][2 * inp + 1], ah[im], bh4 + 2);
                }
            }
        }
        __syncthreads();
    }

    // epilogue: +bias, split to packed bf16 hi/lo planes [ch][tok/2]
    const size_t base = (size_t)w * C_ * 128;
#pragma unroll
    for (int im = 0; im < 2; im++) {
        int gtile = m0 + wm + im * 16;        // 16-aligned; 192 is multiple of 16
        int sec = (gtile >= 192) ? 1 : 0;
        uint32_t* dh = sec ? g_kh : g_qh;
        uint32_t* dl = sec ? g_kl : g_ql;
        int obr = gtile - sec * 192 + (lane >> 2);
        float b0 = qkv_b[gtile + (lane >> 2)];
        float b1 = qkv_b[gtile + (lane >> 2) + 8];
#pragma unroll
        for (int in = 0; in < 8; in++) {
            int n0 = wn + in * 8 + ((lane & 3) << 1);
            int wi = n0 >> 1;
            uint32_t h, l;
            splitbf2(acc[im][in][0] + b0, acc[im][in][1] + b0, h, l);
            dh[base + (size_t)obr * 128 + wi] = h;
            dl[base + (size_t)obr * 128 + wi] = l;
            splitbf2(acc[im][in][2] + b1, acc[im][in][3] + b1, h, l);
            dh[base + (size_t)(obr + 8) * 128 + wi] = h;
            dl[base + (size_t)(obr + 8) * 128 + wi] = l;
        }
    }
}

// ===========================================================================
// K1b: v GEMM (1x tf32). grid (3, 1024), 256 thr, 2 CTA/SM. smem 43008 B.
// A fill = pure copy from pre-converted g_wv.
// ===========================================================================
constexpr size_t SMEM_V_BYTES = (size_t)(64 * 36 + 32 * 264) * 4;  // 43008

__global__ void __launch_bounds__(256, 2) v_kernel(const float* __restrict__ x,
                                                   const float* __restrict__ qkv_b) {
    extern __shared__ uint32_t smv[];
    uint32_t* As = smv;
    uint32_t* Bs = As + 64 * 36;

    const int m0 = blockIdx.x * 64;       // row within W_v [0,192)
    const int w  = blockIdx.y;
    const int b  = w >> 8, wh = (w >> 4) & 15, ww = w & 15;
    const int tid = threadIdx.x, warp = tid >> 5, lane = tid & 31;
    const int wm = (warp >> 2) << 5;
    const int wn = (warp & 3) << 6;
    const float* xw = x + (size_t)b * C_ * IMG + (size_t)(wh * 16) * 256 + ww * 16;

    float acc[2][8][4];
#pragma unroll
    for (int i = 0; i < 2; i++)
#pragma unroll
        for (int j = 0; j < 8; j++)
#pragma unroll
            for (int r = 0; r < 4; r++) acc[i][j][r] = 0.f;

    const int arow = wm + (lane & 7) + ((lane & 8) ? 8 : 0);
    const int asel = (lane & 16) ? 4 : 0;

    for (int k0 = 0; k0 < C_; k0 += 32) {
#pragma unroll
        for (int t = tid; t < 512; t += 256) {
            int r = t >> 3, c4 = (t & 7) << 2;
            *reinterpret_cast<uint4*>(&As[r * 36 + c4]) =
                *reinterpret_cast<const uint4*>(&g_wv[(m0 + r) * C_ + k0 + c4]);
        }
#pragma unroll
        for (int t = tid; t < 2048; t += 256) {
            int c = t >> 6, q = t & 63;
            int i = q >> 2, j4 = (q & 3) << 2;
            float4 v = *reinterpret_cast<const float4*>(
                xw + (size_t)(k0 + c) * IMG + i * 256 + j4);
            uint4 h;
            h.x = f2tf(v.x); h.y = f2tf(v.y); h.z = f2tf(v.z); h.w = f2tf(v.w);
            *reinterpret_cast<uint4*>(&Bs[c * 264 + i * 16 + j4]) = h;
        }
        __syncthreads();

#pragma unroll
        for (int kk = 0; kk < 32; kk += 8) {
            uint32_t a[2][4];
            int awrd = kk + asel;
            ldsm4(a[0], sptr(&As[arow * 36 + awrd]));
            ldsm4(a[1], sptr(&As[(arow + 16) * 36 + awrd]));
#pragma unroll
            for (int in = 0; in < 8; in++) {
                int col = wn + in * 8 + (lane >> 2);
                uint32_t bf[2];
                bf[0] = Bs[(kk + (lane & 3)) * 264 + col];
                bf[1] = Bs[(kk + 4 + (lane & 3)) * 264 + col];
#pragma unroll
                for (int im = 0; im < 2; im++) mma8(acc[im][in], a[im], bf);
            }
        }
        __syncthreads();
    }

    const size_t base = (size_t)w * C_ * NTOK;
#pragma unroll
    for (int im = 0; im < 2; im++) {
        int mr = wm + im * 16 + (lane >> 2);
        float b0 = qkv_b[384 + m0 + mr];
        float b1 = qkv_b[384 + m0 + mr + 8];
#pragma unroll
        for (int in = 0; in < 8; in++) {
            int n0 = wn + in * 8 + ((lane & 3) << 1);
            uint2 r0, r1;
            r0.x = f2tf(acc[im][in][0] + b0); r0.y = f2tf(acc[im][in][1] + b0);
            r1.x = f2tf(acc[im][in][2] + b1); r1.y = f2tf(acc[im][in][3] + b1);
            *reinterpret_cast<uint2*>(&g_v[base + (size_t)(m0 + mr) * NTOK + n0])     = r0;
            *reinterpret_cast<uint2*>(&g_v[base + (size_t)(m0 + mr + 8) * NTOK + n0]) = r1;
        }
    }
}

// ===========================================================================
// K2: attention + fused proj. grid (4, 1024), 512 thr. smem 226304 B.
// ===========================================================================
constexpr int QST = 72;
constexpr int KST = 136;
constexpr int VS2 = 132;
constexpr int SSS = 260;
constexpr int OS2 = 196;
constexpr size_t SMEM_ATTN_BYTES = 56576u * 4;   // 226304

__global__ void __launch_bounds__(512, 1) attn_kernel(const float* __restrict__ x,
                                                      const float* __restrict__ proj_b,
                                                      float* __restrict__ out) {
    extern __shared__ uint32_t sm[];
    uint16_t* Qh16 = (uint16_t*)sm;
    uint16_t* Ql16 = (uint16_t*)(sm + 6912);
    uint16_t* Kh16 = (uint16_t*)(sm + 13824);
    uint16_t* Kl16 = (uint16_t*)(sm + 26880);
    uint32_t* Ssm  = sm + 39936;
    uint32_t* Vs   = sm + 13824;        // [192][132] during PV
    uint32_t* Osm  = sm;                // [64][196] proj phase
    uint32_t* Wsm  = sm + 13824;        // [192][196] proj phase

    const int qb = blockIdx.x, w = blockIdx.y;
    const int b  = w >> 8, wh = (w >> 4) & 15, ww = w & 15;
    const int tid = threadIdx.x, warp = tid >> 5, lane = tid & 31;

    // Q fill: pure copy of packed planes
    {
        const uint32_t* qh = g_qh + (size_t)w * C_ * 128 + qb * 32;
        const uint32_t* ql = g_ql + (size_t)w * C_ * 128 + qb * 32;
        uint32_t* Qhw = (uint32_t*)Qh16;
        uint32_t* Qlw = (uint32_t*)Ql16;
#pragma unroll
        for (int t = tid; t < 192 * 8; t += 512) {
            int r = t >> 3, g4 = (t & 7) << 2;
            *reinterpret_cast<uint4*>(&Qhw[r * 36 + g4]) =
                *reinterpret_cast<const uint4*>(&qh[(size_t)r * 128 + g4]);
            *reinterpret_cast<uint4*>(&Qlw[r * 36 + g4]) =
                *reinterpret_cast<const uint4*>(&ql[(size_t)r * 128 + g4]);
        }
    }

    const int wm = (warp >> 3) << 5;
    const int wk = (warp & 7) << 4;
    const int qk_r = (lane & 7) + ((lane & 16) ? 8 : 0);
    const int qtok = (lane & 8) ? 8 : 0;
    const int kk_r = (lane & 7) + ((lane & 8) ? 8 : 0);
    const int ksel = (lane & 16) ? 8 : 0;

    // ---- S = Q K^T (3x bf16): two 128-key chunks ----
    for (int cb = 0; cb < 2; cb++) {
        {
            const uint32_t* kh = g_kh + (size_t)w * C_ * 128 + cb * 64;
            const uint32_t* kl = g_kl + (size_t)w * C_ * 128 + cb * 64;
            uint32_t* Khw = (uint32_t*)Kh16;
            uint32_t* Klw = (uint32_t*)Kl16;
#pragma unroll
            for (int t = tid; t < 192 * 16; t += 512) {
                int r = t >> 4, g4 = (t & 15) << 2;
                *reinterpret_cast<uint4*>(&Khw[r * 68 + g4]) =
                    *reinterpret_cast<const uint4*>(&kh[(size_t)r * 128 + g4]);
                *reinterpret_cast<uint4*>(&Klw[r * 68 + g4]) =
                    *reinterpret_cast<const uint4*>(&kl[(size_t)r * 128 + g4]);
            }
        }
        __syncthreads();

        float sacc[2][2][4];
#pragma unroll
        for (int i = 0; i < 2; i++)
#pragma unroll
            for (int j = 0; j < 2; j++)
#pragma unroll
                for (int r = 0; r < 4; r++) sacc[i][j][r] = 0.f;

#pragma unroll
        for (int kk2 = 0; kk2 < 192; kk2 += 16) {
            uint32_t ah[2][4], al[2][4], bh4[4], bl4[4];
#pragma unroll
            for (int im = 0; im < 2; im++) {
                int col = wm + im * 16 + qtok;
                ldsm4t(ah[im], sptr(&Qh16[(kk2 + qk_r) * QST + col]));
                ldsm4t(al[im], sptr(&Ql16[(kk2 + qk_r) * QST + col]));
            }
            ldsm4t(bh4, sptr(&Kh16[(kk2 + kk_r) * KST + wk + ksel]));
            ldsm4t(bl4, sptr(&Kl16[(kk2 + kk_r) * KST + wk + ksel]));
#pragma unroll
            for (int im = 0; im < 2; im++) {
                mma16(sacc[im][0], ah[im], bl4);
                mma16(sacc[im][0], al[im], bh4);
                mma16(sacc[im][0], ah[im], bh4);
                mma16(sacc[im][1], ah[im], bl4 + 2);
                mma16(sacc[im][1], al[im], bh4 + 2);
                mma16(sacc[im][1], ah[im], bh4 + 2);
            }
        }
#pragma unroll
        for (int im = 0; im < 2; im++) {
            int r0 = wm + im * 16 + (lane >> 2);
#pragma unroll
            for (int in = 0; in < 2; in++) {
                int c0 = cb * 128 + wk + in * 8 + ((lane & 3) << 1);
                Ssm[r0 * SSS + c0]           = __float_as_uint(sacc[im][in][0]);
                Ssm[r0 * SSS + c0 + 1]       = __float_as_uint(sacc[im][in][1]);
                Ssm[(r0 + 8) * SSS + c0]     = __float_as_uint(sacc[im][in][2]);
                Ssm[(r0 + 8) * SSS + c0 + 1] = __float_as_uint(sacc[im][in][3]);
            }
        }
        __syncthreads();
    }

    // ---- softmax (16 warps x 4 rows of 256); P stored as tf32 ----
#pragma unroll
    for (int rr = 0; rr < 4; rr++) {
        int row = warp * 4 + rr;
        float v[8];
        float mx = -3.0e38f;
#pragma unroll
        for (int i = 0; i < 8; i++) {
            v[i] = __uint_as_float(Ssm[row * SSS + lane + (i << 5)]);
            mx = fmaxf(mx, v[i]);
        }
#pragma unroll
        for (int off = 16; off; off >>= 1) mx = fmaxf(mx, __shfl_xor_sync(0xffffffffu, mx, off));
        float sum = 0.f;
#pragma unroll
        for (int i = 0; i < 8; i++) { v[i] = __expf(v[i] - mx); sum += v[i]; }
#pragma unroll
        for (int off = 16; off; off >>= 1) sum += __shfl_xor_sync(0xffffffffu, sum, off);
        float inv = 1.0f / sum;
#pragma unroll
        for (int i = 0; i < 8; i++) Ssm[row * SSS + lane + (i << 5)] = f2tf(v[i] * inv);
    }
    __syncthreads();

    // ---- O = P @ V (1x tf32): two 128-token chunks; V pure copy ----
    const int wc = (warp & 7) * 24;
    const int arow = wm + (lane & 7) + ((lane & 8) ? 8 : 0);
    const int asel = (lane & 16) ? 4 : 0;
    const int vrow = (lane & 7) + ((lane & 16) ? 8 : 0);
    const int vkw  = (lane & 8) ? 4 : 0;
    float oacc[2][3][4];
#pragma unroll
    for (int i = 0; i < 2; i++)
#pragma unroll
        for (int j = 0; j < 3; j++)
#pragma unroll
            for (int r = 0; r < 4; r++) oacc[i][j][r] = 0.f;

    const size_t vbase = (size_t)w * C_ * NTOK;
    for (int vb = 0; vb < 2; vb++) {
#pragma unroll
        for (int t = tid; t < 192 * 32; t += 512) {
            int ch = t >> 5, t4 = (t & 31) << 2;
            *reinterpret_cast<uint4*>(&Vs[ch * VS2 + t4]) =
                *reinterpret_cast<const uint4*>(&g_v[vbase + (size_t)ch * NTOK + vb * 128 + t4]);
        }
        __syncthreads();

#pragma unroll
        for (int kk = 0; kk < 128; kk += 8) {
            uint32_t a[2][4], b4[4], b2[2];
            int awrd = vb * 128 + kk + asel;
            ldsm4(a[0], sptr(&Ssm[arow * SSS + awrd]));
            ldsm4(a[1], sptr(&Ssm[(arow + 16) * SSS + awrd]));
            ldsm4(b4, sptr(&Vs[(wc + vrow) * VS2 + kk + vkw]));
            ldsm2(b2, sptr(&Vs[(wc + 16 + (lane & 7)) * VS2 + kk + vkw]));
#pragma unroll
            for (int im = 0; im < 2; im++) {
                mma8(oacc[im][0], a[im], b4);
                mma8(oacc[im][1], a[im], b4 + 2);
                mma8(oacc[im][2], a[im], b2);
            }
        }
        __syncthreads();
    }

    // ---- fused proj: O (tf32) -> Osm[tok][ch], Wsm pure copy, GEMM ----
#pragma unroll
    for (int im = 0; im < 2; im++) {
        int q0 = wm + im * 16 + (lane >> 2);
#pragma unroll
        for (int in = 0; in < 3; in++) {
            int c0 = wc + in * 8 + ((lane & 3) << 1);
            Osm[q0 * OS2 + c0]           = f2tf(oacc[im][in][0]);
            Osm[q0 * OS2 + c0 + 1]       = f2tf(oacc[im][in][1]);
            Osm[(q0 + 8) * OS2 + c0]     = f2tf(oacc[im][in][2]);
            Osm[(q0 + 8) * OS2 + c0 + 1] = f2tf(oacc[im][in][3]);
        }
    }
#pragma unroll
    for (int t = tid; t < 192 * 12; t += 512) {
        int r = t / 12, c4 = (t % 12) << 4;
        *reinterpret_cast<uint4*>(&Wsm[r * OS2 + c4]) =
            *reinterpret_cast<const uint4*>(&g_wp[r * C_ + c4]);
        *reinterpret_cast<uint4*>(&Wsm[r * OS2 + c4 + 4]) =
            *reinterpret_cast<const uint4*>(&g_wp[r * C_ + c4 + 4]);
        *reinterpret_cast<uint4*>(&Wsm[r * OS2 + c4 + 8]) =
            *reinterpret_cast<const uint4*>(&g_wp[r * C_ + c4 + 8]);
        *reinterpret_cast<uint4*>(&Wsm[r * OS2 + c4 + 12]) =
            *reinterpret_cast<const uint4*>(&g_wp[r * C_ + c4 + 12]);
    }
    __syncthreads();

    const int wmp = (warp & 3) * 48;
    const int wnp = (warp >> 2) * 16;
    const int parow = (lane & 7) + ((lane & 8) ? 8 : 0);
    const int pasel = (lane & 16) ? 4 : 0;
    const int pbrow = (lane & 7) + ((lane & 16) ? 8 : 0);
    const int pbkw = (lane & 8) ? 4 : 0;

    float pacc[3][2][4];
#pragma unroll
    for (int i = 0; i < 3; i++)
#pragma unroll
        for (int j = 0; j < 2; j++)
#pragma unroll
            for (int r = 0; r < 4; r++) pacc[i][j][r] = 0.f;

#pragma unroll
    for (int kk = 0; kk < 192; kk += 8) {
        uint32_t a[3][4], b4[4];
#pragma unroll
        for (int i = 0; i < 3; i++)
            ldsm4(a[i], sptr(&Wsm[(wmp + i * 16 + parow) * OS2 + kk + pasel]));
        ldsm4(b4, sptr(&Osm[(wnp + pbrow) * OS2 + kk + pbkw]));
#pragma unroll
        for (int i = 0; i < 3; i++) {
            mma8(pacc[i][0], a[i], b4);
            mma8(pacc[i][1], a[i], b4 + 2);
        }
    }

    // epilogue: out = pacc + bias + x (residual)
#pragma unroll
    for (int i = 0; i < 3; i++) {
        int ch = wmp + i * 16 + (lane >> 2);
        float b0 = proj_b[ch];
        float b1 = proj_b[ch + 8];
#pragma unroll
        for (int j = 0; j < 2; j++) {
            int tok = qb * 64 + wnp + j * 8 + ((lane & 3) << 1);
            int ti = tok >> 4, tj = tok & 15;
            size_t g0 = (((size_t)b * C_ + ch) * 256 + wh * 16 + ti) * 256 + ww * 16 + tj;
            size_t g1 = (((size_t)b * C_ + ch + 8) * 256 + wh * 16 + ti) * 256 + ww * 16 + tj;
            float2 x0 = *reinterpret_cast<const float2*>(&x[g0]);
            float2 x1 = *reinterpret_cast<const float2*>(&x[g1]);
            float2 r0, r1;
            r0.x = pacc[i][j][0] + b0 + x0.x;
            r0.y = pacc[i][j][1] + b0 + x0.y;
            r1.x = pacc[i][j][2] + b1 + x1.x;
            r1.y = pacc[i][j][3] + b1 + x1.y;
            *reinterpret_cast<float2*>(&out[g0]) = r0;
            *reinterpret_cast<float2*>(&out[g1]) = r1;
        }
    }
}

// ---------------------------------------------------------------------------
namespace {
struct WarmUp {
    WarmUp() {
        void* p = nullptr;
        cudaGetSymbolAddress(&p, g_qh);
        cudaGetSymbolAddress(&p, g_ql);
        cudaGetSymbolAddress(&p, g_kh);
        cudaGetSymbolAddress(&p, g_kl);
        cudaGetSymbolAddress(&p, g_v);
        cudaGetSymbolAddress(&p, g_wqkh);
        cudaGetSymbolAddress(&p, g_wqkl);
        cudaGetSymbolAddress(&p, g_wv);
        cudaGetSymbolAddress(&p, g_wp);
        cudaFuncSetAttribute(attn_kernel, cudaFuncAttributeMaxDynamicSharedMemorySize,
                             (int)SMEM_ATTN_BYTES);
        cudaFuncSetAttribute(qk_kernel, cudaFuncAttributeMaxDynamicSharedMemorySize,
                             (int)SMEM_QK_BYTES);
        cudaFuncSetAttribute(v_kernel, cudaFuncAttributeMaxDynamicSharedMemorySize,
                             (int)SMEM_V_BYTES);
    }
};
WarmUp warm_;
}  // namespace

extern "C" void kernel_launch(void* const* d_in, const int* in_sizes, int n_in,
                              void* d_out, int out_size) {
    (void)in_sizes; (void)n_in; (void)out_size;
    const float* x      = (const float*)d_in[0];
    const float* qkv_w  = (const float*)d_in[1];
    const float* qkv_b  = (const float*)d_in[2];
    const float* proj_w = (const float*)d_in[3];
    const float* proj_b = (const float*)d_in[4];
    float* out = (float*)d_out;

    cudaFuncSetAttribute(attn_kernel, cudaFuncAttributeMaxDynamicSharedMemorySize,
                         (int)SMEM_ATTN_BYTES);
    cudaFuncSetAttribute(qk_kernel, cudaFuncAttributeMaxDynamicSharedMemorySize,
                         (int)SMEM_QK_BYTES);
    cudaFuncSetAttribute(v_kernel, cudaFuncAttributeMaxDynamicSharedMemorySize,
                         (int)SMEM_V_BYTES);

    split_w_kernel<<<432, 256>>>(qkv_w, proj_w);
    qk_kernel<<<dim3(3, NWIN), 512, SMEM_QK_BYTES>>>(x, qkv_b);
    v_kernel<<<dim3(3, NWIN), 256, SMEM_V_BYTES>>>(x, qkv_b);
    attn_kernel<<<dim3(4, NWIN), 512, SMEM_ATTN_BYTES>>>(x, proj_b, out);
}

// round 14
// speedup vs baseline: 1.2997x; 1.2997x over previous
#include <cuda_runtime.h>
#include <cuda_bf16.h>
#include <cstdint>

// ---------------------------------------------------------------------------
// TransformerBlock: windowed attention, B=4 C=192 H=W=256, 16x16 windows.
//   K0 : prepass — split W_qk (bf16 hi/lo packed); W_v/W_proj -> tf32 bits
//   K1 : merged qkv, grid (9, 1024), 256 thr. q/k stored as packed bf16
//        hi/lo planes [win][ch][tok/2]; v stored as tf32 bits [win][ch][tok].
//   K2 : attention + fused proj, grid (4, 1024), 512 thr.
// (R13 bug fixed: removed stray out-of-bounds As-fill loop in v path.)
// ---------------------------------------------------------------------------

constexpr int C_     = 192;
constexpr int NTOK   = 256;
constexpr int NWIN   = 1024;
constexpr int IMG    = 256 * 256;

__device__ uint32_t g_qh[(size_t)NWIN * C_ * 128];
__device__ uint32_t g_ql[(size_t)NWIN * C_ * 128];
__device__ uint32_t g_kh[(size_t)NWIN * C_ * 128];
__device__ uint32_t g_kl[(size_t)NWIN * C_ * 128];
__device__ uint32_t g_v [(size_t)NWIN * C_ * NTOK];   // tf32 bits [win][ch][tok]
__device__ uint32_t g_wqkh[384 * 96];
__device__ uint32_t g_wqkl[384 * 96];
__device__ uint32_t g_wv[192 * 192];   // W_v as tf32 bits
__device__ uint32_t g_wp[192 * 192];   // W_proj as tf32 bits

__device__ __forceinline__ uint32_t f2tf(float x) {
    uint32_t u;
    asm("cvt.rna.tf32.f32 %0, %1;" : "=r"(u) : "f"(x));
    return u;
}
__device__ __forceinline__ void splitbf2(float x0, float x1, uint32_t& hi, uint32_t& lo) {
    __nv_bfloat16 h0 = __float2bfloat16_rn(x0);
    __nv_bfloat16 h1 = __float2bfloat16_rn(x1);
    __nv_bfloat16 l0 = __float2bfloat16_rn(x0 - __bfloat162float(h0));
    __nv_bfloat16 l1 = __float2bfloat16_rn(x1 - __bfloat162float(h1));
    hi = ((uint32_t)__bfloat16_as_ushort(h1) << 16) | __bfloat16_as_ushort(h0);
    lo = ((uint32_t)__bfloat16_as_ushort(l1) << 16) | __bfloat16_as_ushort(l0);
}
__device__ __forceinline__ uint32_t sptr(const void* p) {
    return (uint32_t)__cvta_generic_to_shared(p);
}
__device__ __forceinline__ void ldsm4(uint32_t* r, uint32_t a) {
    asm volatile("ldmatrix.sync.aligned.m8n8.x4.shared.b16 {%0,%1,%2,%3}, [%4];"
        : "=r"(r[0]), "=r"(r[1]), "=r"(r[2]), "=r"(r[3]) : "r"(a));
}
__device__ __forceinline__ void ldsm2(uint32_t* r, uint32_t a) {
    asm volatile("ldmatrix.sync.aligned.m8n8.x2.shared.b16 {%0,%1}, [%2];"
        : "=r"(r[0]), "=r"(r[1]) : "r"(a));
}
__device__ __forceinline__ void ldsm4t(uint32_t* r, uint32_t a) {
    asm volatile("ldmatrix.sync.aligned.m8n8.x4.trans.shared.b16 {%0,%1,%2,%3}, [%4];"
        : "=r"(r[0]), "=r"(r[1]), "=r"(r[2]), "=r"(r[3]) : "r"(a));
}
__device__ __forceinline__ void mma8(float* d, const uint32_t* a, const uint32_t* b) {
    asm volatile(
        "mma.sync.aligned.m16n8k8.row.col.f32.tf32.tf32.f32 "
        "{%0,%1,%2,%3}, {%4,%5,%6,%7}, {%8,%9}, {%0,%1,%2,%3};\n"
        : "+f"(d[0]), "+f"(d[1]), "+f"(d[2]), "+f"(d[3])
        : "r"(a[0]), "r"(a[1]), "r"(a[2]), "r"(a[3]),
          "r"(b[0]), "r"(b[1]));
}
__device__ __forceinline__ void mma16(float* d, const uint32_t* a, const uint32_t* b) {
    asm volatile(
        "mma.sync.aligned.m16n8k16.row.col.f32.bf16.bf16.f32 "
        "{%0,%1,%2,%3}, {%4,%5,%6,%7}, {%8,%9}, {%0,%1,%2,%3};\n"
        : "+f"(d[0]), "+f"(d[1]), "+f"(d[2]), "+f"(d[3])
        : "r"(a[0]), "r"(a[1]), "r"(a[2]), "r"(a[3]),
          "r"(b[0]), "r"(b[1]));
}

// ===========================================================================
// K0: prepass — split W_qk; convert W_v and W_proj to tf32 bits.
// ===========================================================================
__global__ void split_w_kernel(const float* __restrict__ qkv_w,
                               const float* __restrict__ proj_w) {
    int idx = blockIdx.x * 256 + threadIdx.x;
    if (idx < 384 * 96) {
        int r = idx / 96, c = idx % 96;
        uint32_t h, l;
        splitbf2(qkv_w[r * C_ + 2 * c], qkv_w[r * C_ + 2 * c + 1], h, l);
        g_wqkh[idx] = h;
        g_wqkl[idx] = l;
    } else if (idx < 384 * 96 + 192 * 192) {
        int j = idx - 384 * 96;
        g_wv[j] = f2tf(qkv_w[384 * 192 + j]);
    } else if (idx < 384 * 96 + 2 * 192 * 192) {
        int j = idx - 384 * 96 - 192 * 192;
        g_wp[j] = f2tf(proj_w[j]);
    }
}

// ===========================================================================
// K1: merged qkv. grid (9, 1024), 256 thr, 2 CTA/SM. smem 44032 B.
// ===========================================================================
constexpr int AS3 = 20;
constexpr int BT16 = 264;
constexpr size_t SMEM_QKV_BYTES = (size_t)(2 * 64 * AS3 + 2 * 32 * 132) * 4;  // 44032

__global__ void __launch_bounds__(256, 2) qkv_kernel(const float* __restrict__ x,
                                                     const float* __restrict__ qkv_b) {
    extern __shared__ uint32_t smq[];

    const int w  = blockIdx.y;
    const int b  = w >> 8, wh = (w >> 4) & 15, ww = w & 15;
    const int tid = threadIdx.x, warp = tid >> 5, lane = tid & 31;
    const int wm = (warp >> 2) << 5;
    const int wn = (warp & 3) << 6;
    const float* xw = x + (size_t)b * C_ * IMG + (size_t)(wh * 16) * 256 + ww * 16;

    float acc[2][8][4];
#pragma unroll
    for (int i = 0; i < 2; i++)
#pragma unroll
        for (int j = 0; j < 8; j++)
#pragma unroll
            for (int r = 0; r < 4; r++) acc[i][j][r] = 0.f;

    if (blockIdx.x < 6) {
        // ---------------- q/k path: 3x bf16 ----------------
        uint32_t* Ah = smq;
        uint32_t* Al = Ah + 64 * AS3;
        uint16_t* Bh16 = (uint16_t*)(smq + 2 * 64 * AS3);
        uint16_t* Bl16 = Bh16 + 32 * BT16;
        const int m0 = blockIdx.x * 64;

        const int arow = wm + (lane & 7) + ((lane & 8) ? 8 : 0);
        const int asel = (lane & 16) ? 4 : 0;
        const int brow0 = (lane & 7) + ((lane & 8) ? 8 : 0);
        const int bsel = (lane & 16) ? 8 : 0;

        for (int k0 = 0; k0 < C_; k0 += 32) {
            const int kw0 = k0 >> 1;
#pragma unroll
            for (int t = tid; t < 256; t += 256) {
                int r = t >> 2, c4 = (t & 3) << 2;
                *reinterpret_cast<uint4*>(&Ah[r * AS3 + c4]) =
                    *reinterpret_cast<const uint4*>(&g_wqkh[(m0 + r) * 96 + kw0 + c4]);
                *reinterpret_cast<uint4*>(&Al[r * AS3 + c4]) =
                    *reinterpret_cast<const uint4*>(&g_wqkl[(m0 + r) * 96 + kw0 + c4]);
            }
#pragma unroll
            for (int t = tid; t < 2048; t += 256) {
                int c = t >> 6, q = t & 63;
                int i = q >> 2, j4 = (q & 3) << 2;
                float4 v = *reinterpret_cast<const float4*>(
                    xw + (size_t)(k0 + c) * IMG + i * 256 + j4);
                int tok = i * 16 + j4;
                uint32_t h01, l01, h23, l23;
                splitbf2(v.x, v.y, h01, l01);
                splitbf2(v.z, v.w, h23, l23);
                uint32_t* dh = reinterpret_cast<uint32_t*>(&Bh16[c * BT16 + tok]);
                uint32_t* dl = reinterpret_cast<uint32_t*>(&Bl16[c * BT16 + tok]);
                dh[0] = h01; dh[1] = h23;
                dl[0] = l01; dl[1] = l23;
            }
            __syncthreads();

#pragma unroll
            for (int kk = 0; kk < 32; kk += 16) {
                uint32_t ah[2][4], al[2][4];
                int awrd = (kk >> 1) + asel;
                ldsm4(ah[0], sptr(&Ah[arow * AS3 + awrd]));
                ldsm4(ah[1], sptr(&Ah[(arow + 16) * AS3 + awrd]));
                ldsm4(al[0], sptr(&Al[arow * AS3 + awrd]));
                ldsm4(al[1], sptr(&Al[(arow + 16) * AS3 + awrd]));
                int brow = kk + brow0;
#pragma unroll
                for (int inp = 0; inp < 4; inp++) {
                    int n0 = wn + inp * 16 + bsel;
                    uint32_t bh4[4], bl4[4];
                    ldsm4t(bh4, sptr(&Bh16[brow * BT16 + n0]));
                    ldsm4t(bl4, sptr(&Bl16[brow * BT16 + n0]));
#pragma unroll
                    for (int im = 0; im < 2; im++) {
                        mma16(acc[im][2 * inp],     ah[im], bl4);
                        mma16(acc[im][2 * inp],     al[im], bh4);
                        mma16(acc[im][2 * inp],     ah[im], bh4);
                        mma16(acc[im][2 * inp + 1], ah[im], bl4 + 2);
                        mma16(acc[im][2 * inp + 1], al[im], bh4 + 2);
                        mma16(acc[im][2 * inp + 1], ah[im], bh4 + 2);
                    }
                }
            }
            __syncthreads();
        }

        // epilogue: +bias, split to packed bf16 hi/lo planes [ch][tok/2]
        const int sec = m0 / 192;
        const int ob  = m0 % 192;
        uint32_t* dh = (sec == 0) ? g_qh : g_kh;
        uint32_t* dl = (sec == 0) ? g_ql : g_kl;
        const size_t base = (size_t)w * C_ * 128;
#pragma unroll
        for (int im = 0; im < 2; im++) {
            int mr = wm + im * 16 + (lane >> 2);
            float b0 = qkv_b[m0 + mr];
            float b1 = qkv_b[m0 + mr + 8];
#pragma unroll
            for (int in = 0; in < 8; in++) {
                int n0 = wn + in * 8 + ((lane & 3) << 1);
                int wi = n0 >> 1;
                uint32_t h, l;
                splitbf2(acc[im][in][0] + b0, acc[im][in][1] + b0, h, l);
                dh[base + (size_t)(ob + mr) * 128 + wi] = h;
                dl[base + (size_t)(ob + mr) * 128 + wi] = l;
                splitbf2(acc[im][in][2] + b1, acc[im][in][3] + b1, h, l);
                dh[base + (size_t)(ob + mr + 8) * 128 + wi] = h;
                dl[base + (size_t)(ob + mr + 8) * 128 + wi] = l;
            }
        }
    } else {
        // ---------------- v path: 1x tf32, output tf32 bits [ch][tok] ------
        uint32_t* As = smq;
        uint32_t* Bs = As + 64 * 36;
        const int m0v = (blockIdx.x - 6) * 64;     // row in W_v [0,192)

        const int arow = wm + (lane & 7) + ((lane & 8) ? 8 : 0);
        const int asel = (lane & 16) ? 4 : 0;

        for (int k0 = 0; k0 < C_; k0 += 32) {
            // A: pure copy of pre-converted W_v tile (64 rows x 32 words)
#pragma unroll
            for (int t = tid; t < 512; t += 256) {
                int r = t >> 3, c4 = (t & 7) << 2;
                *reinterpret_cast<uint4*>(&As[r * 36 + c4]) =
                    *reinterpret_cast<const uint4*>(&g_wv[(m0v + r) * C_ + k0 + c4]);
            }
#pragma unroll
            for (int t = tid; t < 2048; t += 256) {
                int c = t >> 6, q = t & 63;
                int i = q >> 2, j4 = (q & 3) << 2;
                float4 v = *reinterpret_cast<const float4*>(
                    xw + (size_t)(k0 + c) * IMG + i * 256 + j4);
                uint4 h;
                h.x = f2tf(v.x); h.y = f2tf(v.y); h.z = f2tf(v.z); h.w = f2tf(v.w);
                *reinterpret_cast<uint4*>(&Bs[c * 264 + i * 16 + j4]) = h;
            }
            __syncthreads();

#pragma unroll
            for (int kk = 0; kk < 32; kk += 8) {
                uint32_t a[2][4];
                int awrd = kk + asel;
                ldsm4(a[0], sptr(&As[arow * 36 + awrd]));
                ldsm4(a[1], sptr(&As[(arow + 16) * 36 + awrd]));
#pragma unroll
                for (int in = 0; in < 8; in++) {
                    int col = wn + in * 8 + (lane >> 2);
                    uint32_t bf[2];
                    bf[0] = Bs[(kk + (lane & 3)) * 264 + col];
                    bf[1] = Bs[(kk + 4 + (lane & 3)) * 264 + col];
#pragma unroll
                    for (int im = 0; im < 2; im++) mma8(acc[im][in], a[im], bf);
                }
            }
            __syncthreads();
        }

        const size_t base = (size_t)w * C_ * NTOK;
#pragma unroll
        for (int im = 0; im < 2; im++) {
            int mr = wm + im * 16 + (lane >> 2);
            float b0 = qkv_b[384 + m0v + mr];
            float b1 = qkv_b[384 + m0v + mr + 8];
#pragma unroll
            for (int in = 0; in < 8; in++) {
                int n0 = wn + in * 8 + ((lane & 3) << 1);
                uint2 r0, r1;
                r0.x = f2tf(acc[im][in][0] + b0); r0.y = f2tf(acc[im][in][1] + b0);
                r1.x = f2tf(acc[im][in][2] + b1); r1.y = f2tf(acc[im][in][3] + b1);
                *reinterpret_cast<uint2*>(&g_v[base + (size_t)(m0v + mr) * NTOK + n0])     = r0;
                *reinterpret_cast<uint2*>(&g_v[base + (size_t)(m0v + mr + 8) * NTOK + n0]) = r1;
            }
        }
    }
}

// ===========================================================================
// K2: attention + fused proj. grid (4, 1024), 512 thr. smem 226304 B.
// ===========================================================================
constexpr int QST = 72;
constexpr int KST = 136;
constexpr int VS2 = 132;
constexpr int SSS = 260;
constexpr int OS2 = 196;
constexpr size_t SMEM_ATTN_BYTES = 56576u * 4;   // 226304

__global__ void __launch_bounds__(512, 1) attn_kernel(const float* __restrict__ x,
                                                      const float* __restrict__ proj_b,
                                                      float* __restrict__ out) {
    extern __shared__ uint32_t sm[];
    uint16_t* Qh16 = (uint16_t*)sm;
    uint16_t* Ql16 = (uint16_t*)(sm + 6912);
    uint16_t* Kh16 = (uint16_t*)(sm + 13824);
    uint16_t* Kl16 = (uint16_t*)(sm + 26880);
    uint32_t* Ssm  = sm + 39936;
    uint32_t* Vs   = sm + 13824;        // [192][132] during PV
    uint32_t* Osm  = sm;                // [64][196] proj phase
    uint32_t* Wsm  = sm + 13824;        // [192][196] proj phase

    const int qb = blockIdx.x, w = blockIdx.y;
    const int b  = w >> 8, wh = (w >> 4) & 15, ww = w & 15;
    const int tid = threadIdx.x, warp = tid >> 5, lane = tid & 31;

    // Q fill: pure copy of packed planes
    {
        const uint32_t* qh = g_qh + (size_t)w * C_ * 128 + qb * 32;
        const uint32_t* ql = g_ql + (size_t)w * C_ * 128 + qb * 32;
        uint32_t* Qhw = (uint32_t*)Qh16;
        uint32_t* Qlw = (uint32_t*)Ql16;
#pragma unroll
        for (int t = tid; t < 192 * 8; t += 512) {
            int r = t >> 3, g4 = (t & 7) << 2;
            *reinterpret_cast<uint4*>(&Qhw[r * 36 + g4]) =
                *reinterpret_cast<const uint4*>(&qh[(size_t)r * 128 + g4]);
            *reinterpret_cast<uint4*>(&Qlw[r * 36 + g4]) =
                *reinterpret_cast<const uint4*>(&ql[(size_t)r * 128 + g4]);
        }
    }

    const int wm = (warp >> 3) << 5;
    const int wk = (warp & 7) << 4;
    const int qk_r = (lane & 7) + ((lane & 16) ? 8 : 0);
    const int qtok = (lane & 8) ? 8 : 0;
    const int kk_r = (lane & 7) + ((lane & 8) ? 8 : 0);
    const int ksel = (lane & 16) ? 8 : 0;

    // ---- S = Q K^T (3x bf16): two 128-key chunks ----
    for (int cb = 0; cb < 2; cb++) {
        {
            const uint32_t* kh = g_kh + (size_t)w * C_ * 128 + cb * 64;
            const uint32_t* kl = g_kl + (size_t)w * C_ * 128 + cb * 64;
            uint32_t* Khw = (uint32_t*)Kh16;
            uint32_t* Klw = (uint32_t*)Kl16;
#pragma unroll
            for (int t = tid; t < 192 * 16; t += 512) {
                int r = t >> 4, g4 = (t & 15) << 2;
                *reinterpret_cast<uint4*>(&Khw[r * 68 + g4]) =
                    *reinterpret_cast<const uint4*>(&kh[(size_t)r * 128 + g4]);
                *reinterpret_cast<uint4*>(&Klw[r * 68 + g4]) =
                    *reinterpret_cast<const uint4*>(&kl[(size_t)r * 128 + g4]);
            }
        }
        __syncthreads();

        float sacc[2][2][4];
#pragma unroll
        for (int i = 0; i < 2; i++)
#pragma unroll
            for (int j = 0; j < 2; j++)
#pragma unroll
                for (int r = 0; r < 4; r++) sacc[i][j][r] = 0.f;

#pragma unroll
        for (int kk2 = 0; kk2 < 192; kk2 += 16) {
            uint32_t ah[2][4], al[2][4], bh4[4], bl4[4];
#pragma unroll
            for (int im = 0; im < 2; im++) {
                int col = wm + im * 16 + qtok;
                ldsm4t(ah[im], sptr(&Qh16[(kk2 + qk_r) * QST + col]));
                ldsm4t(al[im], sptr(&Ql16[(kk2 + qk_r) * QST + col]));
            }
            ldsm4t(bh4, sptr(&Kh16[(kk2 + kk_r) * KST + wk + ksel]));
            ldsm4t(bl4, sptr(&Kl16[(kk2 + kk_r) * KST + wk + ksel]));
#pragma unroll
            for (int im = 0; im < 2; im++) {
                mma16(sacc[im][0], ah[im], bl4);
                mma16(sacc[im][0], al[im], bh4);
                mma16(sacc[im][0], ah[im], bh4);
                mma16(sacc[im][1], ah[im], bl4 + 2);
                mma16(sacc[im][1], al[im], bh4 + 2);
                mma16(sacc[im][1], ah[im], bh4 + 2);
            }
        }
#pragma unroll
        for (int im = 0; im < 2; im++) {
            int r0 = wm + im * 16 + (lane >> 2);
#pragma unroll
            for (int in = 0; in < 2; in++) {
                int c0 = cb * 128 + wk + in * 8 + ((lane & 3) << 1);
                Ssm[r0 * SSS + c0]           = __float_as_uint(sacc[im][in][0]);
                Ssm[r0 * SSS + c0 + 1]       = __float_as_uint(sacc[im][in][1]);
                Ssm[(r0 + 8) * SSS + c0]     = __float_as_uint(sacc[im][in][2]);
                Ssm[(r0 + 8) * SSS + c0 + 1] = __float_as_uint(sacc[im][in][3]);
            }
        }
        __syncthreads();
    }

    // ---- softmax (16 warps x 4 rows of 256); P stored as tf32 ----
#pragma unroll
    for (int rr = 0; rr < 4; rr++) {
        int row = warp * 4 + rr;
        float v[8];
        float mx = -3.0e38f;
#pragma unroll
        for (int i = 0; i < 8; i++) {
            v[i] = __uint_as_float(Ssm[row * SSS + lane + (i << 5)]);
            mx = fmaxf(mx, v[i]);
        }
#pragma unroll
        for (int off = 16; off; off >>= 1) mx = fmaxf(mx, __shfl_xor_sync(0xffffffffu, mx, off));
        float sum = 0.f;
#pragma unroll
        for (int i = 0; i < 8; i++) { v[i] = __expf(v[i] - mx); sum += v[i]; }
#pragma unroll
        for (int off = 16; off; off >>= 1) sum += __shfl_xor_sync(0xffffffffu, sum, off);
        float inv = 1.0f / sum;
#pragma unroll
        for (int i = 0; i < 8; i++) Ssm[row * SSS + lane + (i << 5)] = f2tf(v[i] * inv);
    }
    __syncthreads();

    // ---- O = P @ V (1x tf32): two 128-token chunks; V pure copy ----
    const int wc = (warp & 7) * 24;
    const int arow = wm + (lane & 7) + ((lane & 8) ? 8 : 0);
    const int asel = (lane & 16) ? 4 : 0;
    const int vrow = (lane & 7) + ((lane & 16) ? 8 : 0);
    const int vkw  = (lane & 8) ? 4 : 0;
    float oacc[2][3][4];
#pragma unroll
    for (int i = 0; i < 2; i++)
#pragma unroll
        for (int j = 0; j < 3; j++)
#pragma unroll
            for (int r = 0; r < 4; r++) oacc[i][j][r] = 0.f;

    const size_t vbase = (size_t)w * C_ * NTOK;
    for (int vb = 0; vb < 2; vb++) {
#pragma unroll
        for (int t = tid; t < 192 * 32; t += 512) {
            int ch = t >> 5, t4 = (t & 31) << 2;
            *reinterpret_cast<uint4*>(&Vs[ch * VS2 + t4]) =
                *reinterpret_cast<const uint4*>(&g_v[vbase + (size_t)ch * NTOK + vb * 128 + t4]);
        }
        __syncthreads();

#pragma unroll
        for (int kk = 0; kk < 128; kk += 8) {
            uint32_t a[2][4], b4[4], b2[2];
            int awrd = vb * 128 + kk + asel;
            ldsm4(a[0], sptr(&Ssm[arow * SSS + awrd]));
            ldsm4(a[1], sptr(&Ssm[(arow + 16) * SSS + awrd]));
            ldsm4(b4, sptr(&Vs[(wc + vrow) * VS2 + kk + vkw]));
            ldsm2(b2, sptr(&Vs[(wc + 16 + (lane & 7)) * VS2 + kk + vkw]));
#pragma unroll
            for (int im = 0; im < 2; im++) {
                mma8(oacc[im][0], a[im], b4);
                mma8(oacc[im][1], a[im], b4 + 2);
                mma8(oacc[im][2], a[im], b2);
            }
        }
        __syncthreads();
    }

    // ---- fused proj: O (tf32) -> Osm[tok][ch], Wsm pure copy, GEMM ----
#pragma unroll
    for (int im = 0; im < 2; im++) {
        int q0 = wm + im * 16 + (lane >> 2);
#pragma unroll
        for (int in = 0; in < 3; in++) {
            int c0 = wc + in * 8 + ((lane & 3) << 1);
            Osm[q0 * OS2 + c0]           = f2tf(oacc[im][in][0]);
            Osm[q0 * OS2 + c0 + 1]       = f2tf(oacc[im][in][1]);
            Osm[(q0 + 8) * OS2 + c0]     = f2tf(oacc[im][in][2]);
            Osm[(q0 + 8) * OS2 + c0 + 1] = f2tf(oacc[im][in][3]);
        }
    }
#pragma unroll
    for (int t = tid; t < 192 * 12; t += 512) {
        int r = t / 12, c4 = (t % 12) << 2;
        *reinterpret_cast<uint4*>(&Wsm[r * OS2 + c4]) =
            *reinterpret_cast<const uint4*>(&g_wp[r * C_ + c4]);
        *reinterpret_cast<uint4*>(&Wsm[r * OS2 + c4 + 48]) =
            *reinterpret_cast<const uint4*>(&g_wp[r * C_ + c4 + 48]);
        *reinterpret_cast<uint4*>(&Wsm[r * OS2 + c4 + 96]) =
            *reinterpret_cast<const uint4*>(&g_wp[r * C_ + c4 + 96]);
        *reinterpret_cast<uint4*>(&Wsm[r * OS2 + c4 + 144]) =
            *reinterpret_cast<const uint4*>(&g_wp[r * C_ + c4 + 144]);
    }
    __syncthreads();

    const int wmp = (warp & 3) * 48;
    const int wnp = (warp >> 2) * 16;
    const int parow = (lane & 7) + ((lane & 8) ? 8 : 0);
    const int pasel = (lane & 16) ? 4 : 0;
    const int pbrow = (lane & 7) + ((lane & 16) ? 8 : 0);
    const int pbkw = (lane & 8) ? 4 : 0;

    float pacc[3][2][4];
#pragma unroll
    for (int i = 0; i < 3; i++)
#pragma unroll
        for (int j = 0; j < 2; j++)
#pragma unroll
            for (int r = 0; r < 4; r++) pacc[i][j][r] = 0.f;

#pragma unroll
    for (int kk = 0; kk < 192; kk += 8) {
        uint32_t a[3][4], b4[4];
#pragma unroll
        for (int i = 0; i < 3; i++)
            ldsm4(a[i], sptr(&Wsm[(wmp + i * 16 + parow) * OS2 + kk + pasel]));
        ldsm4(b4, sptr(&Osm[(wnp + pbrow) * OS2 + kk + pbkw]));
#pragma unroll
        for (int i = 0; i < 3; i++) {
            mma8(pacc[i][0], a[i], b4);
            mma8(pacc[i][1], a[i], b4 + 2);
        }
    }

    // epilogue: out = pacc + bias + x (residual)
#pragma unroll
    for (int i = 0; i < 3; i++) {
        int ch = wmp + i * 16 + (lane >> 2);
        float b0 = proj_b[ch];
        float b1 = proj_b[ch + 8];
#pragma unroll
        for (int j = 0; j < 2; j++) {
            int tok = qb * 64 + wnp + j * 8 + ((lane & 3) << 1);
            int ti = tok >> 4, tj = tok & 15;
            size_t g0 = (((size_t)b * C_ + ch) * 256 + wh * 16 + ti) * 256 + ww * 16 + tj;
            size_t g1 = (((size_t)b * C_ + ch + 8) * 256 + wh * 16 + ti) * 256 + ww * 16 + tj;
            float2 x0 = *reinterpret_cast<const float2*>(&x[g0]);
            float2 x1 = *reinterpret_cast<const float2*>(&x[g1]);
            float2 r0, r1;
            r0.x = pacc[i][j][0] + b0 + x0.x;
            r0.y = pacc[i][j][1] + b0 + x0.y;
            r1.x = pacc[i][j][2] + b1 + x1.x;
            r1.y = pacc[i][j][3] + b1 + x1.y;
            *reinterpret_cast<float2*>(&out[g0]) = r0;
            *reinterpret_cast<float2*>(&out[g1]) = r1;
        }
    }
}

// ---------------------------------------------------------------------------
namespace {
struct WarmUp {
    WarmUp() {
        void* p = nullptr;
        cudaGetSymbolAddress(&p, g_qh);
        cudaGetSymbolAddress(&p, g_ql);
        cudaGetSymbolAddress(&p, g_kh);
        cudaGetSymbolAddress(&p, g_kl);
        cudaGetSymbolAddress(&p, g_v);
        cudaGetSymbolAddress(&p, g_wqkh);
        cudaGetSymbolAddress(&p, g_wqkl);
        cudaGetSymbolAddress(&p, g_wv);
        cudaGetSymbolAddress(&p, g_wp);
        cudaFuncSetAttribute(attn_kernel, cudaFuncAttributeMaxDynamicSharedMemorySize,
                             (int)SMEM_ATTN_BYTES);
        cudaFuncSetAttribute(qkv_kernel, cudaFuncAttributeMaxDynamicSharedMemorySize,
                             (int)SMEM_QKV_BYTES);
    }
};
WarmUp warm_;
}  // namespace

extern "C" void kernel_launch(void* const* d_in, const int* in_sizes, int n_in,
                              void* d_out, int out_size) {
    (void)in_sizes; (void)n_in; (void)out_size;
    const float* x      = (const float*)d_in[0];
    const float* qkv_w  = (const float*)d_in[1];
    const float* qkv_b  = (const float*)d_in[2];
    const float* proj_w = (const float*)d_in[3];
    const float* proj_b = (const float*)d_in[4];
    float* out = (float*)d_out;

    cudaFuncSetAttribute(attn_kernel, cudaFuncAttributeMaxDynamicSharedMemorySize,
                         (int)SMEM_ATTN_BYTES);
    cudaFuncSetAttribute(qkv_kernel, cudaFuncAttributeMaxDynamicSharedMemorySize,
                         (int)SMEM_QKV_BYTES);

    split_w_kernel<<<432, 256>>>(qkv_w, proj_w);
    qkv_kernel<<<dim3(9, NWIN), 256, SMEM_QKV_BYTES>>>(x, qkv_b);
    attn_kernel<<<dim3(4, NWIN), 512, SMEM_ATTN_BYTES>>>(x, proj_b, out);
}

// round 15
// speedup vs baseline: 1.3651x; 1.0503x over previous
#include <cuda_runtime.h>
#include <cuda_bf16.h>
#include <cstdint>

// ---------------------------------------------------------------------------
// TransformerBlock: windowed attention, B=4 C=192 H=W=256, 16x16 windows.
//   K0 : prepass — split W_qk (bf16 hi/lo packed); W_v/W_proj -> tf32 bits
//   K1 : merged qkv, grid (9, 1024), 256 thr (unchanged from R14)
//   K2 : attention + fused proj, grid (4, 1024), 512 thr,
//        cp.async double-buffered K (4x64 keys) and V (4x64 tokens) chunks.
// ---------------------------------------------------------------------------

constexpr int C_     = 192;
constexpr int NTOK   = 256;
constexpr int NWIN   = 1024;
constexpr int IMG    = 256 * 256;

__device__ uint32_t g_qh[(size_t)NWIN * C_ * 128];
__device__ uint32_t g_ql[(size_t)NWIN * C_ * 128];
__device__ uint32_t g_kh[(size_t)NWIN * C_ * 128];
__device__ uint32_t g_kl[(size_t)NWIN * C_ * 128];
__device__ uint32_t g_v [(size_t)NWIN * C_ * NTOK];   // tf32 bits [win][ch][tok]
__device__ uint32_t g_wqkh[384 * 96];
__device__ uint32_t g_wqkl[384 * 96];
__device__ uint32_t g_wv[192 * 192];   // W_v as tf32 bits
__device__ uint32_t g_wp[192 * 192];   // W_proj as tf32 bits

__device__ __forceinline__ uint32_t f2tf(float x) {
    uint32_t u;
    asm("cvt.rna.tf32.f32 %0, %1;" : "=r"(u) : "f"(x));
    return u;
}
__device__ __forceinline__ void splitbf2(float x0, float x1, uint32_t& hi, uint32_t& lo) {
    __nv_bfloat16 h0 = __float2bfloat16_rn(x0);
    __nv_bfloat16 h1 = __float2bfloat16_rn(x1);
    __nv_bfloat16 l0 = __float2bfloat16_rn(x0 - __bfloat162float(h0));
    __nv_bfloat16 l1 = __float2bfloat16_rn(x1 - __bfloat162float(h1));
    hi = ((uint32_t)__bfloat16_as_ushort(h1) << 16) | __bfloat16_as_ushort(h0);
    lo = ((uint32_t)__bfloat16_as_ushort(l1) << 16) | __bfloat16_as_ushort(l0);
}
__device__ __forceinline__ uint32_t sptr(const void* p) {
    return (uint32_t)__cvta_generic_to_shared(p);
}
__device__ __forceinline__ void cpa16(uint32_t dst, const void* src) {
    asm volatile("cp.async.cg.shared.global [%0], [%1], 16;" :: "r"(dst), "l"(src));
}
#define CPA_COMMIT() asm volatile("cp.async.commit_group;" ::: "memory")
#define CPA_WAIT0()  asm volatile("cp.async.wait_group 0;" ::: "memory")
#define CPA_WAIT1()  asm volatile("cp.async.wait_group 1;" ::: "memory")

__device__ __forceinline__ void ldsm4(uint32_t* r, uint32_t a) {
    asm volatile("ldmatrix.sync.aligned.m8n8.x4.shared.b16 {%0,%1,%2,%3}, [%4];"
        : "=r"(r[0]), "=r"(r[1]), "=r"(r[2]), "=r"(r[3]) : "r"(a));
}
__device__ __forceinline__ void ldsm2(uint32_t* r, uint32_t a) {
    asm volatile("ldmatrix.sync.aligned.m8n8.x2.shared.b16 {%0,%1}, [%2];"
        : "=r"(r[0]), "=r"(r[1]) : "r"(a));
}
__device__ __forceinline__ void ldsm4t(uint32_t* r, uint32_t a) {
    asm volatile("ldmatrix.sync.aligned.m8n8.x4.trans.shared.b16 {%0,%1,%2,%3}, [%4];"
        : "=r"(r[0]), "=r"(r[1]), "=r"(r[2]), "=r"(r[3]) : "r"(a));
}
__device__ __forceinline__ void mma8(float* d, const uint32_t* a, const uint32_t* b) {
    asm volatile(
        "mma.sync.aligned.m16n8k8.row.col.f32.tf32.tf32.f32 "
        "{%0,%1,%2,%3}, {%4,%5,%6,%7}, {%8,%9}, {%0,%1,%2,%3};\n"
        : "+f"(d[0]), "+f"(d[1]), "+f"(d[2]), "+f"(d[3])
        : "r"(a[0]), "r"(a[1]), "r"(a[2]), "r"(a[3]),
          "r"(b[0]), "r"(b[1]));
}
__device__ __forceinline__ void mma16(float* d, const uint32_t* a, const uint32_t* b) {
    asm volatile(
        "mma.sync.aligned.m16n8k16.row.col.f32.bf16.bf16.f32 "
        "{%0,%1,%2,%3}, {%4,%5,%6,%7}, {%8,%9}, {%0,%1,%2,%3};\n"
        : "+f"(d[0]), "+f"(d[1]), "+f"(d[2]), "+f"(d[3])
        : "r"(a[0]), "r"(a[1]), "r"(a[2]), "r"(a[3]),
          "r"(b[0]), "r"(b[1]));
}

// ===========================================================================
// K0: prepass — split W_qk; convert W_v and W_proj to tf32 bits.
// ===========================================================================
__global__ void split_w_kernel(const float* __restrict__ qkv_w,
                               const float* __restrict__ proj_w) {
    int idx = blockIdx.x * 256 + threadIdx.x;
    if (idx < 384 * 96) {
        int r = idx / 96, c = idx % 96;
        uint32_t h, l;
        splitbf2(qkv_w[r * C_ + 2 * c], qkv_w[r * C_ + 2 * c + 1], h, l);
        g_wqkh[idx] = h;
        g_wqkl[idx] = l;
    } else if (idx < 384 * 96 + 192 * 192) {
        int j = idx - 384 * 96;
        g_wv[j] = f2tf(qkv_w[384 * 192 + j]);
    } else if (idx < 384 * 96 + 2 * 192 * 192) {
        int j = idx - 384 * 96 - 192 * 192;
        g_wp[j] = f2tf(proj_w[j]);
    }
}

// ===========================================================================
// K1: merged qkv. grid (9, 1024), 256 thr, 2 CTA/SM. smem 44032 B. (R14)
// ===========================================================================
constexpr int AS3 = 20;
constexpr int BT16 = 264;
constexpr size_t SMEM_QKV_BYTES = (size_t)(2 * 64 * AS3 + 2 * 32 * 132) * 4;  // 44032

__global__ void __launch_bounds__(256, 2) qkv_kernel(const float* __restrict__ x,
                                                     const float* __restrict__ qkv_b) {
    extern __shared__ uint32_t smq[];

    const int w  = blockIdx.y;
    const int b  = w >> 8, wh = (w >> 4) & 15, ww = w & 15;
    const int tid = threadIdx.x, warp = tid >> 5, lane = tid & 31;
    const int wm = (warp >> 2) << 5;
    const int wn = (warp & 3) << 6;
    const float* xw = x + (size_t)b * C_ * IMG + (size_t)(wh * 16) * 256 + ww * 16;

    float acc[2][8][4];
#pragma unroll
    for (int i = 0; i < 2; i++)
#pragma unroll
        for (int j = 0; j < 8; j++)
#pragma unroll
            for (int r = 0; r < 4; r++) acc[i][j][r] = 0.f;

    if (blockIdx.x < 6) {
        uint32_t* Ah = smq;
        uint32_t* Al = Ah + 64 * AS3;
        uint16_t* Bh16 = (uint16_t*)(smq + 2 * 64 * AS3);
        uint16_t* Bl16 = Bh16 + 32 * BT16;
        const int m0 = blockIdx.x * 64;

        const int arow = wm + (lane & 7) + ((lane & 8) ? 8 : 0);
        const int asel = (lane & 16) ? 4 : 0;
        const int brow0 = (lane & 7) + ((lane & 8) ? 8 : 0);
        const int bsel = (lane & 16) ? 8 : 0;

        for (int k0 = 0; k0 < C_; k0 += 32) {
            const int kw0 = k0 >> 1;
#pragma unroll
            for (int t = tid; t < 256; t += 256) {
                int r = t >> 2, c4 = (t & 3) << 2;
                *reinterpret_cast<uint4*>(&Ah[r * AS3 + c4]) =
                    *reinterpret_cast<const uint4*>(&g_wqkh[(m0 + r) * 96 + kw0 + c4]);
                *reinterpret_cast<uint4*>(&Al[r * AS3 + c4]) =
                    *reinterpret_cast<const uint4*>(&g_wqkl[(m0 + r) * 96 + kw0 + c4]);
            }
#pragma unroll
            for (int t = tid; t < 2048; t += 256) {
                int c = t >> 6, q = t & 63;
                int i = q >> 2, j4 = (q & 3) << 2;
                float4 v = *reinterpret_cast<const float4*>(
                    xw + (size_t)(k0 + c) * IMG + i * 256 + j4);
                int tok = i * 16 + j4;
                uint32_t h01, l01, h23, l23;
                splitbf2(v.x, v.y, h01, l01);
                splitbf2(v.z, v.w, h23, l23);
                uint32_t* dh = reinterpret_cast<uint32_t*>(&Bh16[c * BT16 + tok]);
                uint32_t* dl = reinterpret_cast<uint32_t*>(&Bl16[c * BT16 + tok]);
                dh[0] = h01; dh[1] = h23;
                dl[0] = l01; dl[1] = l23;
            }
            __syncthreads();

#pragma unroll
            for (int kk = 0; kk < 32; kk += 16) {
                uint32_t ah[2][4], al[2][4];
                int awrd = (kk >> 1) + asel;
                ldsm4(ah[0], sptr(&Ah[arow * AS3 + awrd]));
                ldsm4(ah[1], sptr(&Ah[(arow + 16) * AS3 + awrd]));
                ldsm4(al[0], sptr(&Al[arow * AS3 + awrd]));
                ldsm4(al[1], sptr(&Al[(arow + 16) * AS3 + awrd]));
                int brow = kk + brow0;
#pragma unroll
                for (int inp = 0; inp < 4; inp++) {
                    int n0 = wn + inp * 16 + bsel;
                    uint32_t bh4[4], bl4[4];
                    ldsm4t(bh4, sptr(&Bh16[brow * BT16 + n0]));
                    ldsm4t(bl4, sptr(&Bl16[brow * BT16 + n0]));
#pragma unroll
                    for (int im = 0; im < 2; im++) {
                        mma16(acc[im][2 * inp],     ah[im], bl4);
                        mma16(acc[im][2 * inp],     al[im], bh4);
                        mma16(acc[im][2 * inp],     ah[im], bh4);
                        mma16(acc[im][2 * inp + 1], ah[im], bl4 + 2);
                        mma16(acc[im][2 * inp + 1], al[im], bh4 + 2);
                        mma16(acc[im][2 * inp + 1], ah[im], bh4 + 2);
                    }
                }
            }
            __syncthreads();
        }

        const int sec = m0 / 192;
        const int ob  = m0 % 192;
        uint32_t* dh = (sec == 0) ? g_qh : g_kh;
        uint32_t* dl = (sec == 0) ? g_ql : g_kl;
        const size_t base = (size_t)w * C_ * 128;
#pragma unroll
        for (int im = 0; im < 2; im++) {
            int mr = wm + im * 16 + (lane >> 2);
            float b0 = qkv_b[m0 + mr];
            float b1 = qkv_b[m0 + mr + 8];
#pragma unroll
            for (int in = 0; in < 8; in++) {
                int n0 = wn + in * 8 + ((lane & 3) << 1);
                int wi = n0 >> 1;
                uint32_t h, l;
                splitbf2(acc[im][in][0] + b0, acc[im][in][1] + b0, h, l);
                dh[base + (size_t)(ob + mr) * 128 + wi] = h;
                dl[base + (size_t)(ob + mr) * 128 + wi] = l;
                splitbf2(acc[im][in][2] + b1, acc[im][in][3] + b1, h, l);
                dh[base + (size_t)(ob + mr + 8) * 128 + wi] = h;
                dl[base + (size_t)(ob + mr + 8) * 128 + wi] = l;
            }
        }
    } else {
        uint32_t* As = smq;
        uint32_t* Bs = As + 64 * 36;
        const int m0v = (blockIdx.x - 6) * 64;

        const int arow = wm + (lane & 7) + ((lane & 8) ? 8 : 0);
        const int asel = (lane & 16) ? 4 : 0;

        for (int k0 = 0; k0 < C_; k0 += 32) {
#pragma unroll
            for (int t = tid; t < 512; t += 256) {
                int r = t >> 3, c4 = (t & 7) << 2;
                *reinterpret_cast<uint4*>(&As[r * 36 + c4]) =
                    *reinterpret_cast<const uint4*>(&g_wv[(m0v + r) * C_ + k0 + c4]);
            }
#pragma unroll
            for (int t = tid; t < 2048; t += 256) {
                int c = t >> 6, q = t & 63;
                int i = q >> 2, j4 = (q & 3) << 2;
                float4 v = *reinterpret_cast<const float4*>(
                    xw + (size_t)(k0 + c) * IMG + i * 256 + j4);
                uint4 h;
                h.x = f2tf(v.x); h.y = f2tf(v.y); h.z = f2tf(v.z); h.w = f2tf(v.w);
                *reinterpret_cast<uint4*>(&Bs[c * 264 + i * 16 + j4]) = h;
            }
            __syncthreads();

#pragma unroll
            for (int kk = 0; kk < 32; kk += 8) {
                uint32_t a[2][4];
                int awrd = kk + asel;
                ldsm4(a[0], sptr(&As[arow * 36 + awrd]));
                ldsm4(a[1], sptr(&As[(arow + 16) * 36 + awrd]));
#pragma unroll
                for (int in = 0; in < 8; in++) {
                    int col = wn + in * 8 + (lane >> 2);
                    uint32_t bf[2];
                    bf[0] = Bs[(kk + (lane & 3)) * 264 + col];
                    bf[1] = Bs[(kk + 4 + (lane & 3)) * 264 + col];
#pragma unroll
                    for (int im = 0; im < 2; im++) mma8(acc[im][in], a[im], bf);
                }
            }
            __syncthreads();
        }

        const size_t base = (size_t)w * C_ * NTOK;
#pragma unroll
        for (int im = 0; im < 2; im++) {
            int mr = wm + im * 16 + (lane >> 2);
            float b0 = qkv_b[384 + m0v + mr];
            float b1 = qkv_b[384 + m0v + mr + 8];
#pragma unroll
            for (int in = 0; in < 8; in++) {
                int n0 = wn + in * 8 + ((lane & 3) << 1);
                uint2 r0, r1;
                r0.x = f2tf(acc[im][in][0] + b0); r0.y = f2tf(acc[im][in][1] + b0);
                r1.x = f2tf(acc[im][in][2] + b1); r1.y = f2tf(acc[im][in][3] + b1);
                *reinterpret_cast<uint2*>(&g_v[base + (size_t)(m0v + mr) * NTOK + n0])     = r0;
                *reinterpret_cast<uint2*>(&g_v[base + (size_t)(m0v + mr + 8) * NTOK + n0]) = r1;
            }
        }
    }
}

// ===========================================================================
// K2: attention + fused proj. grid (4, 1024), 512 thr. smem 232448 B.
// Word layout: Qh[0,6912) Ql[6912,13824)
//              Kbuf0: Kh 13824, Kl 20736 ; Kbuf1: Kh 27648, Kl 34560
//              Ssm[41472,58112)
// V phase: Vbuf0 @13824 [192][68], Vbuf1 @26880.
// Proj: Osm @0 [64][196], Wsm @13824 [192][196].
// ===========================================================================
constexpr int QST = 72;     // b16 stride (36 words)
constexpr int KST = 72;     // b16 stride per K buffer row
constexpr int VST = 68;     // word stride per V buffer row
constexpr int SSS = 260;
constexpr int OS2 = 196;
constexpr size_t SMEM_ATTN_BYTES = 58112u * 4;   // 232448

__global__ void __launch_bounds__(512, 1) attn_kernel(const float* __restrict__ x,
                                                      const float* __restrict__ proj_b,
                                                      float* __restrict__ out) {
    extern __shared__ uint32_t sm[];
    uint16_t* Qh16 = (uint16_t*)sm;
    uint16_t* Ql16 = (uint16_t*)(sm + 6912);
    uint32_t* Ssm  = sm + 41472;
    uint32_t* Osm  = sm;                // proj phase
    uint32_t* Wsm  = sm + 13824;        // proj phase

    const int qb = blockIdx.x, w = blockIdx.y;
    const int b  = w >> 8, wh = (w >> 4) & 15, ww = w & 15;
    const int tid = threadIdx.x, warp = tid >> 5, lane = tid & 31;

    const uint32_t smb = sptr(sm);      // shared base byte address
    const uint32_t* gqh = g_qh + (size_t)w * C_ * 128 + qb * 32;
    const uint32_t* gql = g_ql + (size_t)w * C_ * 128 + qb * 32;
    const uint32_t* gkh = g_kh + (size_t)w * C_ * 128;
    const uint32_t* gkl = g_kl + (size_t)w * C_ * 128;

    // --- prefetch Q + K chunk0 (group 0), K chunk1 (group 1) ---
    {
        // Q: 192 rows x 32 words
        for (int t = tid; t < 1536; t += 512) {
            int r = t >> 3, c4 = (t & 7) << 2;
            cpa16(smb + (r * 36 + c4) * 4,          gqh + (size_t)r * 128 + c4);
            cpa16(smb + (6912 + r * 36 + c4) * 4,   gql + (size_t)r * 128 + c4);
        }
        // K chunk0 -> buf0
        for (int t = tid; t < 1536; t += 512) {
            int r = t >> 3, c4 = (t & 7) << 2;
            cpa16(smb + (13824 + r * 36 + c4) * 4, gkh + (size_t)r * 128 + c4);
            cpa16(smb + (20736 + r * 36 + c4) * 4, gkl + (size_t)r * 128 + c4);
        }
        CPA_COMMIT();
        // K chunk1 -> buf1
        for (int t = tid; t < 1536; t += 512) {
            int r = t >> 3, c4 = (t & 7) << 2;
            cpa16(smb + (27648 + r * 36 + c4) * 4, gkh + (size_t)r * 128 + 32 + c4);
            cpa16(smb + (34560 + r * 36 + c4) * 4, gkl + (size_t)r * 128 + 32 + c4);
        }
        CPA_COMMIT();
    }

    // S-phase warp grid: 4 tok-groups x 4 key-groups (16 each)
    const int wmS = (warp >> 2) << 4;       // 0,16,32,48
    const int wkS = (warp & 3) << 4;        // 0,16,32,48 within 64-key chunk
    const int qk_r = (lane & 7) + ((lane & 16) ? 8 : 0);
    const int qtok = (lane & 8) ? 8 : 0;
    const int kk_r = (lane & 7) + ((lane & 8) ? 8 : 0);
    const int ksel = (lane & 16) ? 8 : 0;

    // ---- S = Q K^T (3x bf16): four 64-key chunks, double-buffered ----
    for (int cb = 0; cb < 4; cb++) {
        if (cb < 3) { CPA_WAIT1(); } else { CPA_WAIT0(); }
        __syncthreads();

        const uint16_t* KhB = (const uint16_t*)(sm + 13824 + (cb & 1) * 13824);
        const uint16_t* KlB = (const uint16_t*)(sm + 20736 + (cb & 1) * 13824);

        float sacc[2][4];
#pragma unroll
        for (int j = 0; j < 2; j++)
#pragma unroll
            for (int r = 0; r < 4; r++) sacc[j][r] = 0.f;

#pragma unroll
        for (int kk2 = 0; kk2 < 192; kk2 += 16) {
            uint32_t ah[4], al[4], bh4[4], bl4[4];
            int col = wmS + qtok;
            ldsm4t(ah, sptr(&Qh16[(kk2 + qk_r) * QST + col]));
            ldsm4t(al, sptr(&Ql16[(kk2 + qk_r) * QST + col]));
            ldsm4t(bh4, sptr(&KhB[(kk2 + kk_r) * KST + wkS + ksel]));
            ldsm4t(bl4, sptr(&KlB[(kk2 + kk_r) * KST + wkS + ksel]));
            mma16(sacc[0], ah, bl4);
            mma16(sacc[0], al, bh4);
            mma16(sacc[0], ah, bh4);
            mma16(sacc[1], ah, bl4 + 2);
            mma16(sacc[1], al, bh4 + 2);
            mma16(sacc[1], ah, bh4 + 2);
        }
        {
            int r0 = wmS + (lane >> 2);
#pragma unroll
            for (int in = 0; in < 2; in++) {
                int c0 = cb * 64 + wkS + in * 8 + ((lane & 3) << 1);
                Ssm[r0 * SSS + c0]           = __float_as_uint(sacc[in][0]);
                Ssm[r0 * SSS + c0 + 1]       = __float_as_uint(sacc[in][1]);
                Ssm[(r0 + 8) * SSS + c0]     = __float_as_uint(sacc[in][2]);
                Ssm[(r0 + 8) * SSS + c0 + 1] = __float_as_uint(sacc[in][3]);
            }
        }
        __syncthreads();

        if (cb < 2) {
            // issue K chunk cb+2 into buf[cb&1]
            int c = cb + 2;
            uint32_t bh = smb + (13824 + (cb & 1) * 13824) * 4;
            uint32_t bl = smb + (20736 + (cb & 1) * 13824) * 4;
            for (int t = tid; t < 1536; t += 512) {
                int r = t >> 3, c4 = (t & 7) << 2;
                cpa16(bh + (r * 36 + c4) * 4, gkh + (size_t)r * 128 + c * 32 + c4);
                cpa16(bl + (r * 36 + c4) * 4, gkl + (size_t)r * 128 + c * 32 + c4);
            }
            CPA_COMMIT();
        }
    }

    // --- prefetch V chunk0 (buf @13824) and chunk1 (buf @26880) ---
    const uint32_t* gv = g_v + (size_t)w * C_ * NTOK;
    for (int t = tid; t < 3072; t += 512) {
        int r = t >> 4, c4 = (t & 15) << 2;
        cpa16(smb + (13824 + r * VST + c4) * 4, gv + (size_t)r * 256 + c4);
    }
    CPA_COMMIT();
    for (int t = tid; t < 3072; t += 512) {
        int r = t >> 4, c4 = (t & 15) << 2;
        cpa16(smb + (26880 + r * VST + c4) * 4, gv + (size_t)r * 256 + 64 + c4);
    }
    CPA_COMMIT();

    // ---- softmax (16 warps x 4 rows of 256); P stored as tf32 ----
#pragma unroll
    for (int rr = 0; rr < 4; rr++) {
        int row = warp * 4 + rr;
        float v[8];
        float mx = -3.0e38f;
#pragma unroll
        for (int i = 0; i < 8; i++) {
            v[i] = __uint_as_float(Ssm[row * SSS + lane + (i << 5)]);
            mx = fmaxf(mx, v[i]);
        }
#pragma unroll
        for (int off = 16; off; off >>= 1) mx = fmaxf(mx, __shfl_xor_sync(0xffffffffu, mx, off));
        float sum = 0.f;
#pragma unroll
        for (int i = 0; i < 8; i++) { v[i] = __expf(v[i] - mx); sum += v[i]; }
#pragma unroll
        for (int off = 16; off; off >>= 1) sum += __shfl_xor_sync(0xffffffffu, sum, off);
        float inv = 1.0f / sum;
#pragma unroll
        for (int i = 0; i < 8; i++) Ssm[row * SSS + lane + (i << 5)] = f2tf(v[i] * inv);
    }

    // ---- O = P @ V (1x tf32): four 64-token chunks, double-buffered ----
    const int wm2 = (warp >> 3) << 5;
    const int wc = (warp & 7) * 24;
    const int arow = wm2 + (lane & 7) + ((lane & 8) ? 8 : 0);
    const int asel = (lane & 16) ? 4 : 0;
    const int vrow = (lane & 7) + ((lane & 16) ? 8 : 0);
    const int vkw  = (lane & 8) ? 4 : 0;
    float oacc[2][3][4];
#pragma unroll
    for (int i = 0; i < 2; i++)
#pragma unroll
        for (int j = 0; j < 3; j++)
#pragma unroll
            for (int r = 0; r < 4; r++) oacc[i][j][r] = 0.f;

    for (int vb = 0; vb < 4; vb++) {
        if (vb < 3) { CPA_WAIT1(); } else { CPA_WAIT0(); }
        __syncthreads();

        const uint32_t* Vs = sm + 13824 + (vb & 1) * 13056;

#pragma unroll
        for (int kk = 0; kk < 64; kk += 8) {
            uint32_t a[2][4], b4[4], b2[2];
            int awrd = vb * 64 + kk + asel;
            ldsm4(a[0], sptr(&Ssm[arow * SSS + awrd]));
            ldsm4(a[1], sptr(&Ssm[(arow + 16) * SSS + awrd]));
            ldsm4(b4, sptr(&Vs[(wc + vrow) * VST + kk + vkw]));
            ldsm2(b2, sptr(&Vs[(wc + 16 + (lane & 7)) * VST + kk + vkw]));
#pragma unroll
            for (int im = 0; im < 2; im++) {
                mma8(oacc[im][0], a[im], b4);
                mma8(oacc[im][1], a[im], b4 + 2);
                mma8(oacc[im][2], a[im], b2);
            }
        }
        __syncthreads();

        if (vb < 2) {
            int c = vb + 2;
            uint32_t bb = smb + (13824 + (vb & 1) * 13056) * 4;
            for (int t = tid; t < 3072; t += 512) {
                int r = t >> 4, c4 = (t & 15) << 2;
                cpa16(bb + (r * VST + c4) * 4, gv + (size_t)r * 256 + c * 64 + c4);
            }
            CPA_COMMIT();
        }
    }

    // ---- fused proj: O (tf32) -> Osm[tok][ch], Wsm pure copy, GEMM ----
#pragma unroll
    for (int im = 0; im < 2; im++) {
        int q0 = wm2 + im * 16 + (lane >> 2);
#pragma unroll
        for (int in = 0; in < 3; in++) {
            int c0 = wc + in * 8 + ((lane & 3) << 1);
            Osm[q0 * OS2 + c0]           = f2tf(oacc[im][in][0]);
            Osm[q0 * OS2 + c0 + 1]       = f2tf(oacc[im][in][1]);
            Osm[(q0 + 8) * OS2 + c0]     = f2tf(oacc[im][in][2]);
            Osm[(q0 + 8) * OS2 + c0 + 1] = f2tf(oacc[im][in][3]);
        }
    }
#pragma unroll
    for (int t = tid; t < 192 * 12; t += 512) {
        int r = t / 12, c4 = (t % 12) << 2;
        *reinterpret_cast<uint4*>(&Wsm[r * OS2 + c4]) =
            *reinterpret_cast<const uint4*>(&g_wp[r * C_ + c4]);
        *reinterpret_cast<uint4*>(&Wsm[r * OS2 + c4 + 48]) =
            *reinterpret_cast<const uint4*>(&g_wp[r * C_ + c4 + 48]);
        *reinterpret_cast<uint4*>(&Wsm[r * OS2 + c4 + 96]) =
            *reinterpret_cast<const uint4*>(&g_wp[r * C_ + c4 + 96]);
        *reinterpret_cast<uint4*>(&Wsm[r * OS2 + c4 + 144]) =
            *reinterpret_cast<const uint4*>(&g_wp[r * C_ + c4 + 144]);
    }
    __syncthreads();

    const int wmp = (warp & 3) * 48;
    const int wnp = (warp >> 2) * 16;
    const int parow = (lane & 7) + ((lane & 8) ? 8 : 0);
    const int pasel = (lane & 16) ? 4 : 0;
    const int pbrow = (lane & 7) + ((lane & 16) ? 8 : 0);
    const int pbkw = (lane & 8) ? 4 : 0;

    float pacc[3][2][4];
#pragma unroll
    for (int i = 0; i < 3; i++)
#pragma unroll
        for (int j = 0; j < 2; j++)
#pragma unroll
            for (int r = 0; r < 4; r++) pacc[i][j][r] = 0.f;

#pragma unroll
    for (int kk = 0; kk < 192; kk += 8) {
        uint32_t a[3][4], b4[4];
#pragma unroll
        for (int i = 0; i < 3; i++)
            ldsm4(a[i], sptr(&Wsm[(wmp + i * 16 + parow) * OS2 + kk + pasel]));
        ldsm4(b4, sptr(&Osm[(wnp + pbrow) * OS2 + kk + pbkw]));
#pragma unroll
        for (int i = 0; i < 3; i++) {
            mma8(pacc[i][0], a[i], b4);
            mma8(pacc[i][1], a[i], b4 + 2);
        }
    }

    // epilogue: out = pacc + bias + x (residual)
#pragma unroll
    for (int i = 0; i < 3; i++) {
        int ch = wmp + i * 16 + (lane >> 2);
        float b0 = proj_b[ch];
        float b1 = proj_b[ch + 8];
#pragma unroll
        for (int j = 0; j < 2; j++) {
            int tok = qb * 64 + wnp + j * 8 + ((lane & 3) << 1);
            int ti = tok >> 4, tj = tok & 15;
            size_t g0 = (((size_t)b * C_ + ch) * 256 + wh * 16 + ti) * 256 + ww * 16 + tj;
            size_t g1 = (((size_t)b * C_ + ch + 8) * 256 + wh * 16 + ti) * 256 + ww * 16 + tj;
            float2 x0 = *reinterpret_cast<const float2*>(&x[g0]);
            float2 x1 = *reinterpret_cast<const float2*>(&x[g1]);
            float2 r0, r1;
            r0.x = pacc[i][j][0] + b0 + x0.x;
            r0.y = pacc[i][j][1] + b0 + x0.y;
            r1.x = pacc[i][j][2] + b1 + x1.x;
            r1.y = pacc[i][j][3] + b1 + x1.y;
            *reinterpret_cast<float2*>(&out[g0]) = r0;
            *reinterpret_cast<float2*>(&out[g1]) = r1;
        }
    }
}

// ---------------------------------------------------------------------------
namespace {
struct WarmUp {
    WarmUp() {
        void* p = nullptr;
        cudaGetSymbolAddress(&p, g_qh);
        cudaGetSymbolAddress(&p, g_ql);
        cudaGetSymbolAddress(&p, g_kh);
        cudaGetSymbolAddress(&p, g_kl);
        cudaGetSymbolAddress(&p, g_v);
        cudaGetSymbolAddress(&p, g_wqkh);
        cudaGetSymbolAddress(&p, g_wqkl);
        cudaGetSymbolAddress(&p, g_wv);
        cudaGetSymbolAddress(&p, g_wp);
        cudaFuncSetAttribute(attn_kernel, cudaFuncAttributeMaxDynamicSharedMemorySize,
                             (int)SMEM_ATTN_BYTES);
        cudaFuncSetAttribute(qkv_kernel, cudaFuncAttributeMaxDynamicSharedMemorySize,
                             (int)SMEM_QKV_BYTES);
    }
};
WarmUp warm_;
}  // namespace

extern "C" void kernel_launch(void* const* d_in, const int* in_sizes, int n_in,
                              void* d_out, int out_size) {
    (void)in_sizes; (void)n_in; (void)out_size;
    const float* x      = (const float*)d_in[0];
    const float* qkv_w  = (const float*)d_in[1];
    const float* qkv_b  = (const float*)d_in[2];
    const float* proj_w = (const float*)d_in[3];
    const float* proj_b = (const float*)d_in[4];
    float* out = (float*)d_out;

    cudaFuncSetAttribute(attn_kernel, cudaFuncAttributeMaxDynamicSharedMemorySize,
                         (int)SMEM_ATTN_BYTES);
    cudaFuncSetAttribute(qkv_kernel, cudaFuncAttributeMaxDynamicSharedMemorySize,
                         (int)SMEM_QKV_BYTES);

    split_w_kernel<<<432, 256>>>(qkv_w, proj_w);
    qkv_kernel<<<dim3(9, NWIN), 256, SMEM_QKV_BYTES>>>(x, qkv_b);
    attn_kernel<<<dim3(4, NWIN), 512, SMEM_ATTN_BYTES>>>(x, proj_b, out);
}

// round 16
// speedup vs baseline: 1.3913x; 1.0192x over previous
#include <cuda_runtime.h>
#include <cuda_bf16.h>
#include <cstdint>

// ---------------------------------------------------------------------------
// TransformerBlock: windowed attention, B=4 C=192 H=W=256, 16x16 windows.
//   K0a: split W_qkv (all 576 rows) -> bf16 hi/lo; W_proj -> tf32 bits
//   K0b: x prepass — split each window's x into packed bf16 hi/lo planes
//   K1 : unified qkv (3x bf16), grid (9, 1024), 256 thr, cp.async
//        double-buffered pure-copy fills. q/k -> packed planes; v -> tf32.
//   K2 : attention + fused proj (verbatim R15, cp.async pipelined)
// ---------------------------------------------------------------------------

constexpr int C_     = 192;
constexpr int NTOK   = 256;
constexpr int NWIN   = 1024;
constexpr int IMG    = 256 * 256;

__device__ uint32_t g_xh[(size_t)NWIN * C_ * 128];   // x bf16-hi packed [win][ch][tok/2]
__device__ uint32_t g_xl[(size_t)NWIN * C_ * 128];
__device__ uint32_t g_qh[(size_t)NWIN * C_ * 128];
__device__ uint32_t g_ql[(size_t)NWIN * C_ * 128];
__device__ uint32_t g_kh[(size_t)NWIN * C_ * 128];
__device__ uint32_t g_kl[(size_t)NWIN * C_ * 128];
__device__ uint32_t g_v [(size_t)NWIN * C_ * NTOK];  // tf32 bits [win][ch][tok]
__device__ uint32_t g_wqkh[576 * 96];
__device__ uint32_t g_wqkl[576 * 96];
__device__ uint32_t g_wp[192 * 192];                 // W_proj as tf32 bits

__device__ __forceinline__ uint32_t f2tf(float x) {
    uint32_t u;
    asm("cvt.rna.tf32.f32 %0, %1;" : "=r"(u) : "f"(x));
    return u;
}
__device__ __forceinline__ void splitbf2(float x0, float x1, uint32_t& hi, uint32_t& lo) {
    __nv_bfloat16 h0 = __float2bfloat16_rn(x0);
    __nv_bfloat16 h1 = __float2bfloat16_rn(x1);
    __nv_bfloat16 l0 = __float2bfloat16_rn(x0 - __bfloat162float(h0));
    __nv_bfloat16 l1 = __float2bfloat16_rn(x1 - __bfloat162float(h1));
    hi = ((uint32_t)__bfloat16_as_ushort(h1) << 16) | __bfloat16_as_ushort(h0);
    lo = ((uint32_t)__bfloat16_as_ushort(l1) << 16) | __bfloat16_as_ushort(l0);
}
__device__ __forceinline__ uint32_t sptr(const void* p) {
    return (uint32_t)__cvta_generic_to_shared(p);
}
__device__ __forceinline__ void cpa16(uint32_t dst, const void* src) {
    asm volatile("cp.async.cg.shared.global [%0], [%1], 16;" :: "r"(dst), "l"(src));
}
#define CPA_COMMIT() asm volatile("cp.async.commit_group;" ::: "memory")
#define CPA_WAIT0()  asm volatile("cp.async.wait_group 0;" ::: "memory")
#define CPA_WAIT1()  asm volatile("cp.async.wait_group 1;" ::: "memory")

__device__ __forceinline__ void ldsm4(uint32_t* r, uint32_t a) {
    asm volatile("ldmatrix.sync.aligned.m8n8.x4.shared.b16 {%0,%1,%2,%3}, [%4];"
        : "=r"(r[0]), "=r"(r[1]), "=r"(r[2]), "=r"(r[3]) : "r"(a));
}
__device__ __forceinline__ void ldsm2(uint32_t* r, uint32_t a) {
    asm volatile("ldmatrix.sync.aligned.m8n8.x2.shared.b16 {%0,%1}, [%2];"
        : "=r"(r[0]), "=r"(r[1]) : "r"(a));
}
__device__ __forceinline__ void ldsm4t(uint32_t* r, uint32_t a) {
    asm volatile("ldmatrix.sync.aligned.m8n8.x4.trans.shared.b16 {%0,%1,%2,%3}, [%4];"
        : "=r"(r[0]), "=r"(r[1]), "=r"(r[2]), "=r"(r[3]) : "r"(a));
}
__device__ __forceinline__ void mma8(float* d, const uint32_t* a, const uint32_t* b) {
    asm volatile(
        "mma.sync.aligned.m16n8k8.row.col.f32.tf32.tf32.f32 "
        "{%0,%1,%2,%3}, {%4,%5,%6,%7}, {%8,%9}, {%0,%1,%2,%3};\n"
        : "+f"(d[0]), "+f"(d[1]), "+f"(d[2]), "+f"(d[3])
        : "r"(a[0]), "r"(a[1]), "r"(a[2]), "r"(a[3]),
          "r"(b[0]), "r"(b[1]));
}
__device__ __forceinline__ void mma16(float* d, const uint32_t* a, const uint32_t* b) {
    asm volatile(
        "mma.sync.aligned.m16n8k16.row.col.f32.bf16.bf16.f32 "
        "{%0,%1,%2,%3}, {%4,%5,%6,%7}, {%8,%9}, {%0,%1,%2,%3};\n"
        : "+f"(d[0]), "+f"(d[1]), "+f"(d[2]), "+f"(d[3])
        : "r"(a[0]), "r"(a[1]), "r"(a[2]), "r"(a[3]),
          "r"(b[0]), "r"(b[1]));
}

// ===========================================================================
// K0a: weights prepass. 576*96 + 192*192 = 92160 items.
// ===========================================================================
__global__ void split_w_kernel(const float* __restrict__ qkv_w,
                               const float* __restrict__ proj_w) {
    int idx = blockIdx.x * 256 + threadIdx.x;
    if (idx < 576 * 96) {
        int r = idx / 96, c = idx % 96;
        uint32_t h, l;
        splitbf2(qkv_w[r * C_ + 2 * c], qkv_w[r * C_ + 2 * c + 1], h, l);
        g_wqkh[idx] = h;
        g_wqkl[idx] = l;
    } else if (idx < 576 * 96 + 192 * 192) {
        int j = idx - 576 * 96;
        g_wp[j] = f2tf(proj_w[j]);
    }
}

// ===========================================================================
// K0b: x prepass — window gather + bf16 hi/lo split, once per window.
// ===========================================================================
__global__ void __launch_bounds__(256) x_prepass(const float* __restrict__ x) {
    const int w = blockIdx.x;
    const int b = w >> 8, wh = (w >> 4) & 15, ww = w & 15;
    const float* xw = x + (size_t)b * C_ * IMG + (size_t)(wh * 16) * 256 + ww * 16;
    const size_t base = (size_t)w * C_ * 128;
    const int tid = threadIdx.x;
    for (int t = tid; t < 192 * 64; t += 256) {
        int ch = t >> 6, q = t & 63;
        int i = q >> 2, j4 = (q & 3) << 2;
        float4 v = *reinterpret_cast<const float4*>(xw + (size_t)ch * IMG + i * 256 + j4);
        int wi = (i * 16 + j4) >> 1;
        uint32_t h0, l0, h1, l1;
        splitbf2(v.x, v.y, h0, l0);
        splitbf2(v.z, v.w, h1, l1);
        g_xh[base + (size_t)ch * 128 + wi]     = h0;
        g_xh[base + (size_t)ch * 128 + wi + 1] = h1;
        g_xl[base + (size_t)ch * 128 + wi]     = l0;
        g_xl[base + (size_t)ch * 128 + wi + 1] = l1;
    }
}

// ===========================================================================
// K1: unified qkv (3x bf16). grid (9, 1024), 256 thr, 2 CTA/SM.
// smem (words): A bufs 2x(2x64x20)=5120, B bufs 2x(2x32x132)=16896 -> 22016
// ===========================================================================
constexpr int AS3 = 20;
constexpr int BT16 = 264;                 // b16 stride (132 words)
constexpr int QKV_ABUF = 1280;            // words per A plane
constexpr int QKV_BBUF = 4224;            // words per B plane
constexpr size_t SMEM_QKV_BYTES = 22016u * 4;  // 88064

__global__ void __launch_bounds__(256, 2) qkv_kernel(const float* __restrict__ qkv_b) {
    extern __shared__ uint32_t smq[];
    // layout: Ah0[0,1280) Al0[1280,2560) Ah1[2560,3840) Al1[3840,5120)
    //         Bh0[5120,9344) Bl0[9344,13568) Bh1[13568,17792) Bl1[17792,22016)

    const int w  = blockIdx.y;
    const int m0 = blockIdx.x * 64;
    const int tid = threadIdx.x, warp = tid >> 5, lane = tid & 31;
    const int wm = (warp >> 2) << 5;
    const int wn = (warp & 3) << 6;
    const uint32_t smb = sptr(smq);
    const uint32_t* xh = g_xh + (size_t)w * C_ * 128;
    const uint32_t* xl = g_xl + (size_t)w * C_ * 128;

    float acc[2][8][4];
#pragma unroll
    for (int i = 0; i < 2; i++)
#pragma unroll
        for (int j = 0; j < 8; j++)
#pragma unroll
            for (int r = 0; r < 4; r++) acc[i][j][r] = 0.f;

    // fill helper (tile t -> buf t&1)
    auto issue_tile = [&](int t) {
        int bf = t & 1;
        uint32_t ah = smb + (0 + bf * 2560) * 4;
        uint32_t al = smb + (1280 + bf * 2560) * 4;
        uint32_t bh = smb + (5120 + bf * 8448) * 4;
        uint32_t bl = smb + (9344 + bf * 8448) * 4;
        // A: 64 rows x 16 words per plane (256 cpa16 per plane)
        {
            int i = tid;            // 256 threads -> exactly one each
            int r = i >> 2, c4 = (i & 3) << 2;
            cpa16(ah + (r * AS3 + c4) * 4, &g_wqkh[(m0 + r) * 96 + t * 16 + c4]);
            cpa16(al + (r * AS3 + c4) * 4, &g_wqkl[(m0 + r) * 96 + t * 16 + c4]);
        }
        // B: 32 ch x 128 words per plane (1024 cpa16 per plane)
#pragma unroll
        for (int i = tid; i < 1024; i += 256) {
            int r = i >> 5, c4 = (i & 31) << 2;
            cpa16(bh + (r * 132 + c4) * 4, xh + (size_t)(t * 32 + r) * 128 + c4);
            cpa16(bl + (r * 132 + c4) * 4, xl + (size_t)(t * 32 + r) * 128 + c4);
        }
        CPA_COMMIT();
    };

    issue_tile(0);
    issue_tile(1);

    const int arow = wm + (lane & 7) + ((lane & 8) ? 8 : 0);
    const int asel = (lane & 16) ? 4 : 0;
    const int brow0 = (lane & 7) + ((lane & 8) ? 8 : 0);
    const int bsel = (lane & 16) ? 8 : 0;

    for (int cb = 0; cb < 6; cb++) {
        if (cb < 5) { CPA_WAIT1(); } else { CPA_WAIT0(); }
        __syncthreads();

        int bf = cb & 1;
        uint32_t* Ah = smq + bf * 2560;
        uint32_t* Al = Ah + 1280;
        uint16_t* Bh16 = (uint16_t*)(smq + 5120 + bf * 8448);
        uint16_t* Bl16 = (uint16_t*)(smq + 9344 + bf * 8448);

#pragma unroll
        for (int kk = 0; kk < 32; kk += 16) {
            uint32_t ah[2][4], al[2][4];
            int awrd = (kk >> 1) + asel;
            ldsm4(ah[0], sptr(&Ah[arow * AS3 + awrd]));
            ldsm4(ah[1], sptr(&Ah[(arow + 16) * AS3 + awrd]));
            ldsm4(al[0], sptr(&Al[arow * AS3 + awrd]));
            ldsm4(al[1], sptr(&Al[(arow + 16) * AS3 + awrd]));
            int brow = kk + brow0;
#pragma unroll
            for (int inp = 0; inp < 4; inp++) {
                int n0 = wn + inp * 16 + bsel;
                uint32_t bh4[4], bl4[4];
                ldsm4t(bh4, sptr(&Bh16[brow * BT16 + n0]));
                ldsm4t(bl4, sptr(&Bl16[brow * BT16 + n0]));
#pragma unroll
                for (int im = 0; im < 2; im++) {
                    mma16(acc[im][2 * inp],     ah[im], bl4);
                    mma16(acc[im][2 * inp],     al[im], bh4);
                    mma16(acc[im][2 * inp],     ah[im], bh4);
                    mma16(acc[im][2 * inp + 1], ah[im], bl4 + 2);
                    mma16(acc[im][2 * inp + 1], al[im], bh4 + 2);
                    mma16(acc[im][2 * inp + 1], ah[im], bh4 + 2);
                }
            }
        }
        __syncthreads();
        if (cb < 4) issue_tile(cb + 2);
    }

    // epilogues
    if (m0 < 384) {
        // q/k: +bias, split to packed bf16 hi/lo planes [ch][tok/2]
        const int sec = m0 / 192;
        const int ob  = m0 % 192;
        uint32_t* dh = (sec == 0) ? g_qh : g_kh;
        uint32_t* dl = (sec == 0) ? g_ql : g_kl;
        const size_t base = (size_t)w * C_ * 128;
#pragma unroll
        for (int im = 0; im < 2; im++) {
            int mr = wm + im * 16 + (lane >> 2);
            float b0 = qkv_b[m0 + mr];
            float b1 = qkv_b[m0 + mr + 8];
#pragma unroll
            for (int in = 0; in < 8; in++) {
                int n0 = wn + in * 8 + ((lane & 3) << 1);
                int wi = n0 >> 1;
                uint32_t h, l;
                splitbf2(acc[im][in][0] + b0, acc[im][in][1] + b0, h, l);
                dh[base + (size_t)(ob + mr) * 128 + wi] = h;
                dl[base + (size_t)(ob + mr) * 128 + wi] = l;
                splitbf2(acc[im][in][2] + b1, acc[im][in][3] + b1, h, l);
                dh[base + (size_t)(ob + mr + 8) * 128 + wi] = h;
                dl[base + (size_t)(ob + mr + 8) * 128 + wi] = l;
            }
        }
    } else {
        // v: +bias, tf32 bits [ch][tok]
        const int ob = m0 - 384;
        const size_t base = (size_t)w * C_ * NTOK;
#pragma unroll
        for (int im = 0; im < 2; im++) {
            int mr = wm + im * 16 + (lane >> 2);
            float b0 = qkv_b[m0 + mr];
            float b1 = qkv_b[m0 + mr + 8];
#pragma unroll
            for (int in = 0; in < 8; in++) {
                int n0 = wn + in * 8 + ((lane & 3) << 1);
                uint2 r0, r1;
                r0.x = f2tf(acc[im][in][0] + b0); r0.y = f2tf(acc[im][in][1] + b0);
                r1.x = f2tf(acc[im][in][2] + b1); r1.y = f2tf(acc[im][in][3] + b1);
                *reinterpret_cast<uint2*>(&g_v[base + (size_t)(ob + mr) * NTOK + n0])     = r0;
                *reinterpret_cast<uint2*>(&g_v[base + (size_t)(ob + mr + 8) * NTOK + n0]) = r1;
            }
        }
    }
}

// ===========================================================================
// K2: attention + fused proj. grid (4, 1024), 512 thr. smem 232448 B. (R15)
// ===========================================================================
constexpr int QST = 72;
constexpr int KST = 72;
constexpr int VST = 68;
constexpr int SSS = 260;
constexpr int OS2 = 196;
constexpr size_t SMEM_ATTN_BYTES = 58112u * 4;   // 232448

__global__ void __launch_bounds__(512, 1) attn_kernel(const float* __restrict__ x,
                                                      const float* __restrict__ proj_b,
                                                      float* __restrict__ out) {
    extern __shared__ uint32_t sm[];
    uint16_t* Qh16 = (uint16_t*)sm;
    uint16_t* Ql16 = (uint16_t*)(sm + 6912);
    uint32_t* Ssm  = sm + 41472;
    uint32_t* Osm  = sm;
    uint32_t* Wsm  = sm + 13824;

    const int qb = blockIdx.x, w = blockIdx.y;
    const int b  = w >> 8, wh = (w >> 4) & 15, ww = w & 15;
    const int tid = threadIdx.x, warp = tid >> 5, lane = tid & 31;

    const uint32_t smb = sptr(sm);
    const uint32_t* gqh = g_qh + (size_t)w * C_ * 128 + qb * 32;
    const uint32_t* gql = g_ql + (size_t)w * C_ * 128 + qb * 32;
    const uint32_t* gkh = g_kh + (size_t)w * C_ * 128;
    const uint32_t* gkl = g_kl + (size_t)w * C_ * 128;

    {
        for (int t = tid; t < 1536; t += 512) {
            int r = t >> 3, c4 = (t & 7) << 2;
            cpa16(smb + (r * 36 + c4) * 4,          gqh + (size_t)r * 128 + c4);
            cpa16(smb + (6912 + r * 36 + c4) * 4,   gql + (size_t)r * 128 + c4);
        }
        for (int t = tid; t < 1536; t += 512) {
            int r = t >> 3, c4 = (t & 7) << 2;
            cpa16(smb + (13824 + r * 36 + c4) * 4, gkh + (size_t)r * 128 + c4);
            cpa16(smb + (20736 + r * 36 + c4) * 4, gkl + (size_t)r * 128 + c4);
        }
        CPA_COMMIT();
        for (int t = tid; t < 1536; t += 512) {
            int r = t >> 3, c4 = (t & 7) << 2;
            cpa16(smb + (27648 + r * 36 + c4) * 4, gkh + (size_t)r * 128 + 32 + c4);
            cpa16(smb + (34560 + r * 36 + c4) * 4, gkl + (size_t)r * 128 + 32 + c4);
        }
        CPA_COMMIT();
    }

    const int wmS = (warp >> 2) << 4;
    const int wkS = (warp & 3) << 4;
    const int qk_r = (lane & 7) + ((lane & 16) ? 8 : 0);
    const int qtok = (lane & 8) ? 8 : 0;
    const int kk_r = (lane & 7) + ((lane & 8) ? 8 : 0);
    const int ksel = (lane & 16) ? 8 : 0;

    for (int cb = 0; cb < 4; cb++) {
        if (cb < 3) { CPA_WAIT1(); } else { CPA_WAIT0(); }
        __syncthreads();

        const uint16_t* KhB = (const uint16_t*)(sm + 13824 + (cb & 1) * 13824);
        const uint16_t* KlB = (const uint16_t*)(sm + 20736 + (cb & 1) * 13824);

        float sacc[2][4];
#pragma unroll
        for (int j = 0; j < 2; j++)
#pragma unroll
            for (int r = 0; r < 4; r++) sacc[j][r] = 0.f;

#pragma unroll
        for (int kk2 = 0; kk2 < 192; kk2 += 16) {
            uint32_t ah[4], al[4], bh4[4], bl4[4];
            int col = wmS + qtok;
            ldsm4t(ah, sptr(&Qh16[(kk2 + qk_r) * QST + col]));
            ldsm4t(al, sptr(&Ql16[(kk2 + qk_r) * QST + col]));
            ldsm4t(bh4, sptr(&KhB[(kk2 + kk_r) * KST + wkS + ksel]));
            ldsm4t(bl4, sptr(&KlB[(kk2 + kk_r) * KST + wkS + ksel]));
            mma16(sacc[0], ah, bl4);
            mma16(sacc[0], al, bh4);
            mma16(sacc[0], ah, bh4);
            mma16(sacc[1], ah, bl4 + 2);
            mma16(sacc[1], al, bh4 + 2);
            mma16(sacc[1], ah, bh4 + 2);
        }
        {
            int r0 = wmS + (lane >> 2);
#pragma unroll
            for (int in = 0; in < 2; in++) {
                int c0 = cb * 64 + wkS + in * 8 + ((lane & 3) << 1);
                Ssm[r0 * SSS + c0]           = __float_as_uint(sacc[in][0]);
                Ssm[r0 * SSS + c0 + 1]       = __float_as_uint(sacc[in][1]);
                Ssm[(r0 + 8) * SSS + c0]     = __float_as_uint(sacc[in][2]);
                Ssm[(r0 + 8) * SSS + c0 + 1] = __float_as_uint(sacc[in][3]);
            }
        }
        __syncthreads();

        if (cb < 2) {
            int c = cb + 2;
            uint32_t bh = smb + (13824 + (cb & 1) * 13824) * 4;
            uint32_t bl = smb + (20736 + (cb & 1) * 13824) * 4;
            for (int t = tid; t < 1536; t += 512) {
                int r = t >> 3, c4 = (t & 7) << 2;
                cpa16(bh + (r * 36 + c4) * 4, gkh + (size_t)r * 128 + c * 32 + c4);
                cpa16(bl + (r * 36 + c4) * 4, gkl + (size_t)r * 128 + c * 32 + c4);
            }
            CPA_COMMIT();
        }
    }

    const uint32_t* gv = g_v + (size_t)w * C_ * NTOK;
    for (int t = tid; t < 3072; t += 512) {
        int r = t >> 4, c4 = (t & 15) << 2;
        cpa16(smb + (13824 + r * VST + c4) * 4, gv + (size_t)r * 256 + c4);
    }
    CPA_COMMIT();
    for (int t = tid; t < 3072; t += 512) {
        int r = t >> 4, c4 = (t & 15) << 2;
        cpa16(smb + (26880 + r * VST + c4) * 4, gv + (size_t)r * 256 + 64 + c4);
    }
    CPA_COMMIT();

#pragma unroll
    for (int rr = 0; rr < 4; rr++) {
        int row = warp * 4 + rr;
        float v[8];
        float mx = -3.0e38f;
#pragma unroll
        for (int i = 0; i < 8; i++) {
            v[i] = __uint_as_float(Ssm[row * SSS + lane + (i << 5)]);
            mx = fmaxf(mx, v[i]);
        }
#pragma unroll
        for (int off = 16; off; off >>= 1) mx = fmaxf(mx, __shfl_xor_sync(0xffffffffu, mx, off));
        float sum = 0.f;
#pragma unroll
        for (int i = 0; i < 8; i++) { v[i] = __expf(v[i] - mx); sum += v[i]; }
#pragma unroll
        for (int off = 16; off; off >>= 1) sum += __shfl_xor_sync(0xffffffffu, sum, off);
        float inv = 1.0f / sum;
#pragma unroll
        for (int i = 0; i < 8; i++) Ssm[row * SSS + lane + (i << 5)] = f2tf(v[i] * inv);
    }

    const int wm2 = (warp >> 3) << 5;
    const int wc = (warp & 7) * 24;
    const int arow = wm2 + (lane & 7) + ((lane & 8) ? 8 : 0);
    const int asel = (lane & 16) ? 4 : 0;
    const int vrow = (lane & 7) + ((lane & 16) ? 8 : 0);
    const int vkw  = (lane & 8) ? 4 : 0;
    float oacc[2][3][4];
#pragma unroll
    for (int i = 0; i < 2; i++)
#pragma unroll
        for (int j = 0; j < 3; j++)
#pragma unroll
            for (int r = 0; r < 4; r++) oacc[i][j][r] = 0.f;

    for (int vb = 0; vb < 4; vb++) {
        if (vb < 3) { CPA_WAIT1(); } else { CPA_WAIT0(); }
        __syncthreads();

        const uint32_t* Vs = sm + 13824 + (vb & 1) * 13056;

#pragma unroll
        for (int kk = 0; kk < 64; kk += 8) {
            uint32_t a[2][4], b4[4], b2[2];
            int awrd = vb * 64 + kk + asel;
            ldsm4(a[0], sptr(&Ssm[arow * SSS + awrd]));
            ldsm4(a[1], sptr(&Ssm[(arow + 16) * SSS + awrd]));
            ldsm4(b4, sptr(&Vs[(wc + vrow) * VST + kk + vkw]));
            ldsm2(b2, sptr(&Vs[(wc + 16 + (lane & 7)) * VST + kk + vkw]));
#pragma unroll
            for (int im = 0; im < 2; im++) {
                mma8(oacc[im][0], a[im], b4);
                mma8(oacc[im][1], a[im], b4 + 2);
                mma8(oacc[im][2], a[im], b2);
            }
        }
        __syncthreads();

        if (vb < 2) {
            int c = vb + 2;
            uint32_t bb = smb + (13824 + (vb & 1) * 13056) * 4;
            for (int t = tid; t < 3072; t += 512) {
                int r = t >> 4, c4 = (t & 15) << 2;
                cpa16(bb + (r * VST + c4) * 4, gv + (size_t)r * 256 + c * 64 + c4);
            }
            CPA_COMMIT();
        }
    }

#pragma unroll
    for (int im = 0; im < 2; im++) {
        int q0 = wm2 + im * 16 + (lane >> 2);
#pragma unroll
        for (int in = 0; in < 3; in++) {
            int c0 = wc + in * 8 + ((lane & 3) << 1);
            Osm[q0 * OS2 + c0]           = f2tf(oacc[im][in][0]);
            Osm[q0 * OS2 + c0 + 1]       = f2tf(oacc[im][in][1]);
            Osm[(q0 + 8) * OS2 + c0]     = f2tf(oacc[im][in][2]);
            Osm[(q0 + 8) * OS2 + c0 + 1] = f2tf(oacc[im][in][3]);
        }
    }
#pragma unroll
    for (int t = tid; t < 192 * 12; t += 512) {
        int r = t / 12, c4 = (t % 12) << 2;
        *reinterpret_cast<uint4*>(&Wsm[r * OS2 + c4]) =
            *reinterpret_cast<const uint4*>(&g_wp[r * C_ + c4]);
        *reinterpret_cast<uint4*>(&Wsm[r * OS2 + c4 + 48]) =
            *reinterpret_cast<const uint4*>(&g_wp[r * C_ + c4 + 48]);
        *reinterpret_cast<uint4*>(&Wsm[r * OS2 + c4 + 96]) =
            *reinterpret_cast<const uint4*>(&g_wp[r * C_ + c4 + 96]);
        *reinterpret_cast<uint4*>(&Wsm[r * OS2 + c4 + 144]) =
            *reinterpret_cast<const uint4*>(&g_wp[r * C_ + c4 + 144]);
    }
    __syncthreads();

    const int wmp = (warp & 3) * 48;
    const int wnp = (warp >> 2) * 16;
    const int parow = (lane & 7) + ((lane & 8) ? 8 : 0);
    const int pasel = (lane & 16) ? 4 : 0;
    const int pbrow = (lane & 7) + ((lane & 16) ? 8 : 0);
    const int pbkw = (lane & 8) ? 4 : 0;

    float pacc[3][2][4];
#pragma unroll
    for (int i = 0; i < 3; i++)
#pragma unroll
        for (int j = 0; j < 2; j++)
#pragma unroll
            for (int r = 0; r < 4; r++) pacc[i][j][r] = 0.f;

#pragma unroll
    for (int kk = 0; kk < 192; kk += 8) {
        uint32_t a[3][4], b4[4];
#pragma unroll
        for (int i = 0; i < 3; i++)
            ldsm4(a[i], sptr(&Wsm[(wmp + i * 16 + parow) * OS2 + kk + pasel]));
        ldsm4(b4, sptr(&Osm[(wnp + pbrow) * OS2 + kk + pbkw]));
#pragma unroll
        for (int i = 0; i < 3; i++) {
            mma8(pacc[i][0], a[i], b4);
            mma8(pacc[i][1], a[i], b4 + 2);
        }
    }

#pragma unroll
    for (int i = 0; i < 3; i++) {
        int ch = wmp + i * 16 + (lane >> 2);
        float b0 = proj_b[ch];
        float b1 = proj_b[ch + 8];
#pragma unroll
        for (int j = 0; j < 2; j++) {
            int tok = qb * 64 + wnp + j * 8 + ((lane & 3) << 1);
            int ti = tok >> 4, tj = tok & 15;
            size_t g0 = (((size_t)b * C_ + ch) * 256 + wh * 16 + ti) * 256 + ww * 16 + tj;
            size_t g1 = (((size_t)b * C_ + ch + 8) * 256 + wh * 16 + ti) * 256 + ww * 16 + tj;
            float2 x0 = *reinterpret_cast<const float2*>(&x[g0]);
            float2 x1 = *reinterpret_cast<const float2*>(&x[g1]);
            float2 r0, r1;
            r0.x = pacc[i][j][0] + b0 + x0.x;
            r0.y = pacc[i][j][1] + b0 + x0.y;
            r1.x = pacc[i][j][2] + b1 + x1.x;
            r1.y = pacc[i][j][3] + b1 + x1.y;
            *reinterpret_cast<float2*>(&out[g0]) = r0;
            *reinterpret_cast<float2*>(&out[g1]) = r1;
        }
    }
}

// ---------------------------------------------------------------------------
namespace {
struct WarmUp {
    WarmUp() {
        void* p = nullptr;
        cudaGetSymbolAddress(&p, g_xh);
        cudaGetSymbolAddress(&p, g_xl);
        cudaGetSymbolAddress(&p, g_qh);
        cudaGetSymbolAddress(&p, g_ql);
        cudaGetSymbolAddress(&p, g_kh);
        cudaGetSymbolAddress(&p, g_kl);
        cudaGetSymbolAddress(&p, g_v);
        cudaGetSymbolAddress(&p, g_wqkh);
        cudaGetSymbolAddress(&p, g_wqkl);
        cudaGetSymbolAddress(&p, g_wp);
        cudaFuncSetAttribute(attn_kernel, cudaFuncAttributeMaxDynamicSharedMemorySize,
                             (int)SMEM_ATTN_BYTES);
        cudaFuncSetAttribute(qkv_kernel, cudaFuncAttributeMaxDynamicSharedMemorySize,
                             (int)SMEM_QKV_BYTES);
    }
};
WarmUp warm_;
}  // namespace

extern "C" void kernel_launch(void* const* d_in, const int* in_sizes, int n_in,
                              void* d_out, int out_size) {
    (void)in_sizes; (void)n_in; (void)out_size;
    const float* x      = (const float*)d_in[0];
    const float* qkv_w  = (const float*)d_in[1];
    const float* qkv_b  = (const float*)d_in[2];
    const float* proj_w = (const float*)d_in[3];
    const float* proj_b = (const float*)d_in[4];
    float* out = (float*)d_out;

    cudaFuncSetAttribute(attn_kernel, cudaFuncAttributeMaxDynamicSharedMemorySize,
                         (int)SMEM_ATTN_BYTES);
    cudaFuncSetAttribute(qkv_kernel, cudaFuncAttributeMaxDynamicSharedMemorySize,
                         (int)SMEM_QKV_BYTES);

    split_w_kernel<<<360, 256>>>(qkv_w, proj_w);
    x_prepass<<<NWIN, 256>>>(x);
    qkv_kernel<<<dim3(9, NWIN), 256, SMEM_QKV_BYTES>>>(qkv_b);
    attn_kernel<<<dim3(4, NWIN), 512, SMEM_ATTN_BYTES>>>(x, proj_b, out);
}